// round 6
// baseline (speedup 1.0000x reference)
#include <cuda_runtime.h>
#include <cstdint>

#define NU 100000
#define NI 100000
#define D  128
#define EMAX 810000
#define NROWS 100000

typedef unsigned long long u64;

// ---------------- scratch ----------------------------------------------------
__device__ float g_acc_f [(size_t)NU * D];
__device__ float g_acc_rb[(size_t)NU * D];
__device__ float g_acc_r [(size_t)NI * D];
__device__ int   g_hist_f [NU];
__device__ int   g_hist_rb[NU];
__device__ int   g_hist_r [NI];
__device__ int   g_ptr_f [NU + 1];
__device__ int   g_ptr_rb[NU + 1];
__device__ int   g_ptr_r [NI + 1];
__device__ int   g_cur_f [NU];
__device__ int   g_cur_rb[NU];
__device__ int   g_cur_r [NI];
__device__ int   g_srcl_f [EMAX];
__device__ int   g_srcl_rb[EMAX];
__device__ int   g_srcl_r [EMAX];

// ---------------- zero histograms --------------------------------------------
__global__ void zero_hist_kernel() {
    int i = blockIdx.x * blockDim.x + threadIdx.x;
    if (i < NU) { g_hist_f[i] = 0; g_hist_rb[i] = 0; g_hist_r[i] = 0; }
}

// ---------------- fused histogram ---------------------------------------------
__global__ __launch_bounds__(256) void hist3_kernel(
    const int* __restrict__ d0, const int* __restrict__ d1,
    const int* __restrict__ d2, int E0, int E1, int E2)
{
    int et = blockIdx.y;
    const int* dst = (et == 0) ? d0 : (et == 1) ? d1 : d2;
    int* hist = (et == 0) ? g_hist_f : (et == 1) ? g_hist_rb : g_hist_r;
    int E = (et == 0) ? E0 : (et == 1) ? E1 : E2;
    int i = blockIdx.x * blockDim.x + threadIdx.x;
    if (i < E) atomicAdd(&hist[dst[i]], 1);
}

// ---------------- per-etype exclusive scan ------------------------------------
__global__ __launch_bounds__(1024) void scan_kernel(int n)
{
    const int* hist; int* ptr; int* cur;
    if      (blockIdx.x == 0) { hist = g_hist_f;  ptr = g_ptr_f;  cur = g_cur_f;  }
    else if (blockIdx.x == 1) { hist = g_hist_rb; ptr = g_ptr_rb; cur = g_cur_rb; }
    else                      { hist = g_hist_r;  ptr = g_ptr_r;  cur = g_cur_r;  }

    const int T = 1024;
    int chunk = (n + T - 1) / T;
    int lo = threadIdx.x * chunk;
    int hi = lo + chunk; if (hi > n) hi = n;
    if (lo > n) lo = n;

    int s = 0;
    for (int i = lo; i < hi; i++) s += hist[i];

    __shared__ int warpsum[32];
    int lane = threadIdx.x & 31, wid = threadIdx.x >> 5;
    int incl = s;
#pragma unroll
    for (int off = 1; off < 32; off <<= 1) {
        int t = __shfl_up_sync(0xffffffffu, incl, off);
        if (lane >= off) incl += t;
    }
    if (lane == 31) warpsum[wid] = incl;
    __syncthreads();
    if (wid == 0) {
        int w = warpsum[lane];
#pragma unroll
        for (int off = 1; off < 32; off <<= 1) {
            int t = __shfl_up_sync(0xffffffffu, w, off);
            if (lane >= off) w += t;
        }
        warpsum[lane] = w;
    }
    __syncthreads();
    int excl = incl - s + (wid ? warpsum[wid - 1] : 0);
    for (int i = lo; i < hi; i++) {
        ptr[i] = excl; cur[i] = excl; excl += hist[i];
    }
    if (threadIdx.x == 0) ptr[n] = warpsum[31];
}

// ---------------- fused permute -----------------------------------------------
__global__ __launch_bounds__(256) void permute3_kernel(
    const int* __restrict__ s0, const int* __restrict__ d0,
    const int* __restrict__ s1, const int* __restrict__ d1,
    const int* __restrict__ s2, const int* __restrict__ d2,
    int E0, int E1, int E2)
{
    int et = blockIdx.y;
    const int* src = (et == 0) ? s0 : (et == 1) ? s1 : s2;
    const int* dst = (et == 0) ? d0 : (et == 1) ? d1 : d2;
    int* cur = (et == 0) ? g_cur_f : (et == 1) ? g_cur_rb : g_cur_r;
    int* srclist = (et == 0) ? g_srcl_f : (et == 1) ? g_srcl_rb : g_srcl_r;
    int E = (et == 0) ? E0 : (et == 1) ? E1 : E2;
    int i = blockIdx.x * blockDim.x + threadIdx.x;
    if (i < E) {
        int d = dst[i];
        int p = atomicAdd(&cur[d], 1);
        srclist[p] = src[i];
    }
}

// ---------------- fused gather: 2 nodes per warp, shared latency chain --------
__global__ __launch_bounds__(256) void gather3_kernel(
    const float4* __restrict__ feat_u, const float4* __restrict__ feat_i)
{
    int et = blockIdx.y;
    const float4* feat = (et == 1) ? feat_i : feat_u;
    const int* ptr = (et == 0) ? g_ptr_f : (et == 1) ? g_ptr_rb : g_ptr_r;
    const int* srclist = (et == 0) ? g_srcl_f : (et == 1) ? g_srcl_rb : g_srcl_r;
    float4* acc = (float4*)((et == 0) ? g_acc_f : (et == 1) ? g_acc_rb : g_acc_r);

    int warp = (blockIdx.x * 256 + threadIdx.x) >> 5;
    int lane = threadIdx.x & 31;
    int nodeA = warp * 2;
    if (nodeA >= NROWS) return;
    int nodeB = nodeA + 1;
    bool hasB = (nodeB < NROWS);

    // one coalesced load covers ptr[nodeA], ptr[nodeA+1], ptr[nodeA+2]
    int p = 0;
    if (lane < 3) p = __ldg(&ptr[nodeA + lane]);
    int begA = __shfl_sync(0xffffffffu, p, 0);
    int midA = __shfl_sync(0xffffffffu, p, 1);
    int endB = hasB ? __shfl_sync(0xffffffffu, p, 2) : midA;
    int degA = midA - begA;
    int degB = endB - midA;

    float4 sA = make_float4(0.f, 0.f, 0.f, 0.f);
    float4 sB = make_float4(0.f, 0.f, 0.f, 0.f);
    int eA = begA, eB = midA;

    while (eA < midA || eB < endB) {
        int nA = midA - eA; if (nA > 8) nA = 8;
        int nB = endB - eB; if (nB > 8) nB = 8;

        // lane-parallel index fetch: lanes 0..7 -> node A, 8..15 -> node B
        int idx = 0;
        if (lane < 8) {
            if (lane < nA) idx = __ldg(&srclist[eA + lane]);
        } else if (lane < 16) {
            int j = lane - 8;
            if (j < nB) idx = __ldg(&srclist[eB + j]);
        }

        // broadcast indices, issue up to 16 independent row loads
        float4 vA[8], vB[8];
#pragma unroll
        for (int j = 0; j < 8; j++) {
            int sj = __shfl_sync(0xffffffffu, idx, j);
            if (j < nA) vA[j] = feat[(size_t)sj * 32 + lane];
        }
#pragma unroll
        for (int j = 0; j < 8; j++) {
            int sj = __shfl_sync(0xffffffffu, idx, 8 + j);
            if (j < nB) vB[j] = feat[(size_t)sj * 32 + lane];
        }
#pragma unroll
        for (int j = 0; j < 8; j++) {
            if (j < nA) {
                sA.x += vA[j].x; sA.y += vA[j].y;
                sA.z += vA[j].z; sA.w += vA[j].w;
            }
        }
#pragma unroll
        for (int j = 0; j < 8; j++) {
            if (j < nB) {
                sB.x += vB[j].x; sB.y += vB[j].y;
                sB.z += vB[j].z; sB.w += vB[j].w;
            }
        }
        eA += nA; eB += nB;
    }

    float invA = __fdividef(1.0f, (float)(degA > 0 ? degA : 1));
    sA.x *= invA; sA.y *= invA; sA.z *= invA; sA.w *= invA;
    acc[(size_t)nodeA * 32 + lane] = sA;
    if (hasB) {
        float invB = __fdividef(1.0f, (float)(degB > 0 ? degB : 1));
        sB.x *= invB; sB.y *= invB; sB.z *= invB; sB.w *= invB;
        acc[(size_t)nodeB * 32 + lane] = sB;
    }
}

// ---------------- packed fp32x2 helpers --------------------------------------
__device__ __forceinline__ u64 ffma2(u64 a, u64 b, u64 c) {
    u64 d;
    asm("fma.rn.f32x2 %0, %1, %2, %3;" : "=l"(d) : "l"(a), "l"(b), "l"(c));
    return d;
}
__device__ __forceinline__ u64 dup2(float x) {
    u64 r;
    asm("mov.b64 %0, {%1, %1};" : "=l"(r) : "f"(x));
    return r;
}
union F2U { u64 u; float2 f; };

// ---------------- GEMM: BM=128, BN=128, BK=16, 256 thr, 8x8 thread tile -------
#define ASTRIDE 132

__global__ __launch_bounds__(256, 2) void gemm_big(
    float* __restrict__ out_user, float* __restrict__ out_item,
    const float* __restrict__ W_f, const float* __restrict__ b_f,
    const float* __restrict__ W_rb, const float* __restrict__ b_rb,
    const float* __restrict__ W_r, const float* __restrict__ b_r)
{
    __shared__ __align__(16) float As[16][ASTRIDE];
    __shared__ __align__(16) float Ws[16][128];

    const int tid = threadIdx.x;
    const int tx = tid & 15;
    const int ty = tid >> 4;
    const int row0 = blockIdx.x * 128;
    const bool user = (blockIdx.y == 0);
    const int nkt = user ? 16 : 8;
    float* out = user ? out_user : out_item;

    const int a_row = tid >> 1;
    const int a_k   = (tid & 1) * 8;
    const int garow = row0 + a_row;
    const int w_n = tid & 127;
    const int w_k = (tid >> 7) * 8;

    u64 C[8][4];
#pragma unroll
    for (int m = 0; m < 8; m++)
#pragma unroll
        for (int c = 0; c < 4; c++) C[m][c] = 0ull;

    for (int kt = 0; kt < nkt; kt++) {
        const int seg = kt >> 3;
        const int kc = (kt & 7) * 16;
        const float* acc = user ? (seg ? g_acc_rb : g_acc_f) : g_acc_r;
        const float* W = user ? (seg ? W_rb : W_f) : W_r;

        float4 a0 = make_float4(0.f, 0.f, 0.f, 0.f), a1 = a0;
        if (garow < NROWS) {
            a0 = *reinterpret_cast<const float4*>(acc + (size_t)garow * D + kc + a_k);
            a1 = *reinterpret_cast<const float4*>(acc + (size_t)garow * D + kc + a_k + 4);
        }
        float4 w0 = *reinterpret_cast<const float4*>(W + (size_t)w_n * D + kc + w_k);
        float4 w1 = *reinterpret_cast<const float4*>(W + (size_t)w_n * D + kc + w_k + 4);

        __syncthreads();
        As[a_k + 0][a_row] = a0.x;
        As[a_k + 1][a_row] = a0.y;
        As[a_k + 2][a_row] = a0.z;
        As[a_k + 3][a_row] = a0.w;
        As[a_k + 4][a_row] = a1.x;
        As[a_k + 5][a_row] = a1.y;
        As[a_k + 6][a_row] = a1.z;
        As[a_k + 7][a_row] = a1.w;
        Ws[w_k + 0][w_n] = w0.x;
        Ws[w_k + 1][w_n] = w0.y;
        Ws[w_k + 2][w_n] = w0.z;
        Ws[w_k + 3][w_n] = w0.w;
        Ws[w_k + 4][w_n] = w1.x;
        Ws[w_k + 5][w_n] = w1.y;
        Ws[w_k + 6][w_n] = w1.z;
        Ws[w_k + 7][w_n] = w1.w;
        __syncthreads();

#pragma unroll
        for (int k = 0; k < 16; k++) {
            float4 ar0 = *reinterpret_cast<const float4*>(&As[k][ty * 8]);
            float4 ar1 = *reinterpret_cast<const float4*>(&As[k][ty * 8 + 4]);
            ulonglong2 wlo = *reinterpret_cast<const ulonglong2*>(&Ws[k][tx * 4]);
            ulonglong2 whi = *reinterpret_cast<const ulonglong2*>(&Ws[k][64 + tx * 4]);
            u64 ad[8];
            ad[0] = dup2(ar0.x); ad[1] = dup2(ar0.y);
            ad[2] = dup2(ar0.z); ad[3] = dup2(ar0.w);
            ad[4] = dup2(ar1.x); ad[5] = dup2(ar1.y);
            ad[6] = dup2(ar1.z); ad[7] = dup2(ar1.w);
#pragma unroll
            for (int m = 0; m < 8; m++) {
                C[m][0] = ffma2(ad[m], wlo.x, C[m][0]);
                C[m][1] = ffma2(ad[m], wlo.y, C[m][1]);
                C[m][2] = ffma2(ad[m], whi.x, C[m][2]);
                C[m][3] = ffma2(ad[m], whi.y, C[m][3]);
            }
        }
    }

    const float* bias0 = user ? b_f : b_r;
    const int* cnt0 = user ? g_hist_f : g_hist_r;
    float4 blo0 = *reinterpret_cast<const float4*>(bias0 + tx * 4);
    float4 bhi0 = *reinterpret_cast<const float4*>(bias0 + 64 + tx * 4);
    float4 blo1 = make_float4(0.f, 0.f, 0.f, 0.f), bhi1 = blo1;
    if (user) {
        blo1 = *reinterpret_cast<const float4*>(b_rb + tx * 4);
        bhi1 = *reinterpret_cast<const float4*>(b_rb + 64 + tx * 4);
    }
#pragma unroll
    for (int m = 0; m < 8; m++) {
        int r = row0 + ty * 8 + m;
        if (r >= NROWS) continue;
        float m0 = (cnt0[r] > 0) ? 1.0f : 0.0f;
        float m1 = (user && g_hist_rb[r] > 0) ? 1.0f : 0.0f;
        F2U c0, c1, c2, c3;
        c0.u = C[m][0]; c1.u = C[m][1]; c2.u = C[m][2]; c3.u = C[m][3];
        float4 olo, ohi;
        olo.x = c0.f.x + blo0.x * m0 + blo1.x * m1;
        olo.y = c0.f.y + blo0.y * m0 + blo1.y * m1;
        olo.z = c1.f.x + blo0.z * m0 + blo1.z * m1;
        olo.w = c1.f.y + blo0.w * m0 + blo1.w * m1;
        ohi.x = c2.f.x + bhi0.x * m0 + bhi1.x * m1;
        ohi.y = c2.f.y + bhi0.y * m0 + bhi1.y * m1;
        ohi.z = c3.f.x + bhi0.z * m0 + bhi1.z * m1;
        ohi.w = c3.f.y + bhi0.w * m0 + bhi1.w * m1;
        *reinterpret_cast<float4*>(out + (size_t)r * D + tx * 4) = olo;
        *reinterpret_cast<float4*>(out + (size_t)r * D + 64 + tx * 4) = ohi;
    }
}

// ---------------- launch ------------------------------------------------------
extern "C" void kernel_launch(void* const* d_in, const int* in_sizes, int n_in,
                              void* d_out, int out_size)
{
    const float* feat_user = (const float*)d_in[0];
    const float* feat_item = (const float*)d_in[1];
    const float* W_f  = (const float*)d_in[2];
    const float* b_f  = (const float*)d_in[3];
    const float* W_r  = (const float*)d_in[4];
    const float* b_r  = (const float*)d_in[5];
    const float* W_rb = (const float*)d_in[6];
    const float* b_rb = (const float*)d_in[7];
    const int* src_f  = (const int*)d_in[8];
    const int* dst_f  = (const int*)d_in[9];
    const int* src_r  = (const int*)d_in[10];
    const int* dst_r  = (const int*)d_in[11];
    const int* src_rb = (const int*)d_in[12];
    const int* dst_rb = (const int*)d_in[13];
    const int E_f  = in_sizes[8];
    const int E_rb = in_sizes[12];
    const int E_r  = in_sizes[10];

    float* out_user = (float*)d_out;
    float* out_item = (float*)d_out + (size_t)NU * D;

    int Emax = E_f > E_rb ? E_f : E_rb;
    if (E_r > Emax) Emax = E_r;

    zero_hist_kernel<<<(NU + 255) / 256, 256>>>();

    {
        dim3 g((Emax + 255) / 256, 3);
        hist3_kernel<<<g, 256>>>(dst_f, dst_rb, dst_r, E_f, E_rb, E_r);
    }

    scan_kernel<<<3, 1024>>>(NU);

    {
        dim3 g((Emax + 255) / 256, 3);
        permute3_kernel<<<g, 256>>>(src_f, dst_f, src_rb, dst_rb, src_r, dst_r,
                                    E_f, E_rb, E_r);
    }

    {
        // 2 nodes per warp -> NROWS/2 warps per etype
        int warps = (NROWS + 1) / 2;
        dim3 g((warps * 32 + 255) / 256, 3);
        gather3_kernel<<<g, 256>>>((const float4*)feat_user,
                                   (const float4*)feat_item);
    }

    {
        dim3 g((NROWS + 127) / 128, 2);
        gemm_big<<<g, 256>>>(out_user, out_item,
                             W_f, b_f, W_rb, b_rb, W_r, b_r);
    }
}

// round 7
// speedup vs baseline: 1.3660x; 1.3660x over previous
#include <cuda_runtime.h>
#include <cstdint>

#define NU 100000
#define NI 100000
#define D  128
#define EMAX 810000
#define NROWS 100000
#define HALF ((NROWS + 1) / 2)

typedef unsigned long long u64;

// ---------------- scratch ----------------------------------------------------
__device__ float g_acc_f [(size_t)NU * D];
__device__ float g_acc_rb[(size_t)NU * D];
__device__ float g_acc_r [(size_t)NI * D];
__device__ int   g_hist_f [NU];
__device__ int   g_hist_rb[NU];
__device__ int   g_hist_r [NI];
__device__ int   g_ptr_f [NU + 1];
__device__ int   g_ptr_rb[NU + 1];
__device__ int   g_ptr_r [NI + 1];
__device__ int   g_cur_f [NU];
__device__ int   g_cur_rb[NU];
__device__ int   g_cur_r [NI];
__device__ int   g_srcl_f [EMAX];
__device__ int   g_srcl_rb[EMAX];
__device__ int   g_srcl_r [EMAX];

// ---------------- zero histograms --------------------------------------------
__global__ void zero_hist_kernel() {
    int i = blockIdx.x * blockDim.x + threadIdx.x;
    if (i < NU) { g_hist_f[i] = 0; g_hist_rb[i] = 0; g_hist_r[i] = 0; }
}

// ---------------- fused histogram ---------------------------------------------
__global__ __launch_bounds__(256) void hist3_kernel(
    const int* __restrict__ d0, const int* __restrict__ d1,
    const int* __restrict__ d2, int E0, int E1, int E2)
{
    int et = blockIdx.y;
    const int* dst = (et == 0) ? d0 : (et == 1) ? d1 : d2;
    int* hist = (et == 0) ? g_hist_f : (et == 1) ? g_hist_rb : g_hist_r;
    int E = (et == 0) ? E0 : (et == 1) ? E1 : E2;
    int i = blockIdx.x * blockDim.x + threadIdx.x;
    if (i < E) atomicAdd(&hist[dst[i]], 1);
}

// ---------------- per-etype exclusive scan ------------------------------------
__global__ __launch_bounds__(1024) void scan_kernel(int n)
{
    const int* hist; int* ptr; int* cur;
    if      (blockIdx.x == 0) { hist = g_hist_f;  ptr = g_ptr_f;  cur = g_cur_f;  }
    else if (blockIdx.x == 1) { hist = g_hist_rb; ptr = g_ptr_rb; cur = g_cur_rb; }
    else                      { hist = g_hist_r;  ptr = g_ptr_r;  cur = g_cur_r;  }

    const int T = 1024;
    int chunk = (n + T - 1) / T;
    int lo = threadIdx.x * chunk;
    int hi = lo + chunk; if (hi > n) hi = n;
    if (lo > n) lo = n;

    int s = 0;
    for (int i = lo; i < hi; i++) s += hist[i];

    __shared__ int warpsum[32];
    int lane = threadIdx.x & 31, wid = threadIdx.x >> 5;
    int incl = s;
#pragma unroll
    for (int off = 1; off < 32; off <<= 1) {
        int t = __shfl_up_sync(0xffffffffu, incl, off);
        if (lane >= off) incl += t;
    }
    if (lane == 31) warpsum[wid] = incl;
    __syncthreads();
    if (wid == 0) {
        int w = warpsum[lane];
#pragma unroll
        for (int off = 1; off < 32; off <<= 1) {
            int t = __shfl_up_sync(0xffffffffu, w, off);
            if (lane >= off) w += t;
        }
        warpsum[lane] = w;
    }
    __syncthreads();
    int excl = incl - s + (wid ? warpsum[wid - 1] : 0);
    for (int i = lo; i < hi; i++) {
        ptr[i] = excl; cur[i] = excl; excl += hist[i];
    }
    if (threadIdx.x == 0) ptr[n] = warpsum[31];
}

// ---------------- fused permute -----------------------------------------------
__global__ __launch_bounds__(256) void permute3_kernel(
    const int* __restrict__ s0, const int* __restrict__ d0,
    const int* __restrict__ s1, const int* __restrict__ d1,
    const int* __restrict__ s2, const int* __restrict__ d2,
    int E0, int E1, int E2)
{
    int et = blockIdx.y;
    const int* src = (et == 0) ? s0 : (et == 1) ? s1 : s2;
    const int* dst = (et == 0) ? d0 : (et == 1) ? d1 : d2;
    int* cur = (et == 0) ? g_cur_f : (et == 1) ? g_cur_rb : g_cur_r;
    int* srclist = (et == 0) ? g_srcl_f : (et == 1) ? g_srcl_rb : g_srcl_r;
    int E = (et == 0) ? E0 : (et == 1) ? E1 : E2;
    int i = blockIdx.x * blockDim.x + threadIdx.x;
    if (i < E) {
        int d = dst[i];
        int p = atomicAdd(&cur[d], 1);
        srclist[p] = src[i];
    }
}

// ---------------- fused gather: 2 interleaved nodes per warp ------------------
// Node A = w, node B = w + HALF. Uniform scalar index loads (broadcast LDG),
// batch 4 per node -> up to 8 independent feature-row loads in flight.
__global__ __launch_bounds__(256) void gather3_kernel(
    const float4* __restrict__ feat_u, const float4* __restrict__ feat_i)
{
    int et = blockIdx.y;
    const float4* feat = (et == 1) ? feat_i : feat_u;
    const int* ptr = (et == 0) ? g_ptr_f : (et == 1) ? g_ptr_rb : g_ptr_r;
    const int* srclist = (et == 0) ? g_srcl_f : (et == 1) ? g_srcl_rb : g_srcl_r;
    float4* acc = (float4*)((et == 0) ? g_acc_f : (et == 1) ? g_acc_rb : g_acc_r);

    int warp = (blockIdx.x * 256 + threadIdx.x) >> 5;
    int lane = threadIdx.x & 31;
    if (warp >= HALF) return;
    int nodeA = warp;
    int nodeB = warp + HALF;
    bool hasB = (nodeB < NROWS);

    int begA = __ldg(&ptr[nodeA]);
    int endA = __ldg(&ptr[nodeA + 1]);
    int begB = 0, endB = 0;
    if (hasB) {
        begB = __ldg(&ptr[nodeB]);
        endB = __ldg(&ptr[nodeB + 1]);
    }
    int degA = endA - begA;
    int degB = endB - begB;

    float4 sA = make_float4(0.f, 0.f, 0.f, 0.f);
    float4 sB = make_float4(0.f, 0.f, 0.f, 0.f);
    int eA = begA, eB = begB;

    while (eA < endA || eB < endB) {
        int nA = endA - eA; if (nA > 4) nA = 4; if (nA < 0) nA = 0;
        int nB = endB - eB; if (nB > 4) nB = 4; if (nB < 0) nB = 0;

        int iA[4], iB[4];
#pragma unroll
        for (int j = 0; j < 4; j++) if (j < nA) iA[j] = __ldg(&srclist[eA + j]);
#pragma unroll
        for (int j = 0; j < 4; j++) if (j < nB) iB[j] = __ldg(&srclist[eB + j]);

        float4 vA[4], vB[4];
#pragma unroll
        for (int j = 0; j < 4; j++)
            if (j < nA) vA[j] = feat[(size_t)iA[j] * 32 + lane];
#pragma unroll
        for (int j = 0; j < 4; j++)
            if (j < nB) vB[j] = feat[(size_t)iB[j] * 32 + lane];

#pragma unroll
        for (int j = 0; j < 4; j++)
            if (j < nA) {
                sA.x += vA[j].x; sA.y += vA[j].y;
                sA.z += vA[j].z; sA.w += vA[j].w;
            }
#pragma unroll
        for (int j = 0; j < 4; j++)
            if (j < nB) {
                sB.x += vB[j].x; sB.y += vB[j].y;
                sB.z += vB[j].z; sB.w += vB[j].w;
            }
        eA += nA; eB += nB;
    }

    float invA = __fdividef(1.0f, (float)(degA > 0 ? degA : 1));
    sA.x *= invA; sA.y *= invA; sA.z *= invA; sA.w *= invA;
    acc[(size_t)nodeA * 32 + lane] = sA;
    if (hasB) {
        float invB = __fdividef(1.0f, (float)(degB > 0 ? degB : 1));
        sB.x *= invB; sB.y *= invB; sB.z *= invB; sB.w *= invB;
        acc[(size_t)nodeB * 32 + lane] = sB;
    }
}

// ---------------- packed fp32x2 helpers --------------------------------------
__device__ __forceinline__ u64 ffma2(u64 a, u64 b, u64 c) {
    u64 d;
    asm("fma.rn.f32x2 %0, %1, %2, %3;" : "=l"(d) : "l"(a), "l"(b), "l"(c));
    return d;
}
__device__ __forceinline__ u64 dup2(float x) {
    u64 r;
    asm("mov.b64 %0, {%1, %1};" : "=l"(r) : "f"(x));
    return r;
}
union F2U { u64 u; float2 f; };

// ---------------- GEMM: BM=128, BN=128, BK=16, 256 thr, 8x8 thread tile -------
#define ASTRIDE 132

__global__ __launch_bounds__(256, 2) void gemm_big(
    float* __restrict__ out_user, float* __restrict__ out_item,
    const float* __restrict__ W_f, const float* __restrict__ b_f,
    const float* __restrict__ W_rb, const float* __restrict__ b_rb,
    const float* __restrict__ W_r, const float* __restrict__ b_r)
{
    __shared__ __align__(16) float As[16][ASTRIDE];
    __shared__ __align__(16) float Ws[16][128];

    const int tid = threadIdx.x;
    const int tx = tid & 15;
    const int ty = tid >> 4;
    const int row0 = blockIdx.x * 128;
    const bool user = (blockIdx.y == 0);
    const int nkt = user ? 16 : 8;
    float* out = user ? out_user : out_item;

    const int a_row = tid >> 1;
    const int a_k   = (tid & 1) * 8;
    const int garow = row0 + a_row;
    const int w_n = tid & 127;
    const int w_k = (tid >> 7) * 8;

    u64 C[8][4];
#pragma unroll
    for (int m = 0; m < 8; m++)
#pragma unroll
        for (int c = 0; c < 4; c++) C[m][c] = 0ull;

    for (int kt = 0; kt < nkt; kt++) {
        const int seg = kt >> 3;
        const int kc = (kt & 7) * 16;
        const float* acc = user ? (seg ? g_acc_rb : g_acc_f) : g_acc_r;
        const float* W = user ? (seg ? W_rb : W_f) : W_r;

        float4 a0 = make_float4(0.f, 0.f, 0.f, 0.f), a1 = a0;
        if (garow < NROWS) {
            a0 = *reinterpret_cast<const float4*>(acc + (size_t)garow * D + kc + a_k);
            a1 = *reinterpret_cast<const float4*>(acc + (size_t)garow * D + kc + a_k + 4);
        }
        float4 w0 = *reinterpret_cast<const float4*>(W + (size_t)w_n * D + kc + w_k);
        float4 w1 = *reinterpret_cast<const float4*>(W + (size_t)w_n * D + kc + w_k + 4);

        __syncthreads();
        As[a_k + 0][a_row] = a0.x;
        As[a_k + 1][a_row] = a0.y;
        As[a_k + 2][a_row] = a0.z;
        As[a_k + 3][a_row] = a0.w;
        As[a_k + 4][a_row] = a1.x;
        As[a_k + 5][a_row] = a1.y;
        As[a_k + 6][a_row] = a1.z;
        As[a_k + 7][a_row] = a1.w;
        Ws[w_k + 0][w_n] = w0.x;
        Ws[w_k + 1][w_n] = w0.y;
        Ws[w_k + 2][w_n] = w0.z;
        Ws[w_k + 3][w_n] = w0.w;
        Ws[w_k + 4][w_n] = w1.x;
        Ws[w_k + 5][w_n] = w1.y;
        Ws[w_k + 6][w_n] = w1.z;
        Ws[w_k + 7][w_n] = w1.w;
        __syncthreads();

#pragma unroll
        for (int k = 0; k < 16; k++) {
            float4 ar0 = *reinterpret_cast<const float4*>(&As[k][ty * 8]);
            float4 ar1 = *reinterpret_cast<const float4*>(&As[k][ty * 8 + 4]);
            ulonglong2 wlo = *reinterpret_cast<const ulonglong2*>(&Ws[k][tx * 4]);
            ulonglong2 whi = *reinterpret_cast<const ulonglong2*>(&Ws[k][64 + tx * 4]);
            u64 ad[8];
            ad[0] = dup2(ar0.x); ad[1] = dup2(ar0.y);
            ad[2] = dup2(ar0.z); ad[3] = dup2(ar0.w);
            ad[4] = dup2(ar1.x); ad[5] = dup2(ar1.y);
            ad[6] = dup2(ar1.z); ad[7] = dup2(ar1.w);
#pragma unroll
            for (int m = 0; m < 8; m++) {
                C[m][0] = ffma2(ad[m], wlo.x, C[m][0]);
                C[m][1] = ffma2(ad[m], wlo.y, C[m][1]);
                C[m][2] = ffma2(ad[m], whi.x, C[m][2]);
                C[m][3] = ffma2(ad[m], whi.y, C[m][3]);
            }
        }
    }

    const float* bias0 = user ? b_f : b_r;
    const int* cnt0 = user ? g_hist_f : g_hist_r;
    float4 blo0 = *reinterpret_cast<const float4*>(bias0 + tx * 4);
    float4 bhi0 = *reinterpret_cast<const float4*>(bias0 + 64 + tx * 4);
    float4 blo1 = make_float4(0.f, 0.f, 0.f, 0.f), bhi1 = blo1;
    if (user) {
        blo1 = *reinterpret_cast<const float4*>(b_rb + tx * 4);
        bhi1 = *reinterpret_cast<const float4*>(b_rb + 64 + tx * 4);
    }
#pragma unroll
    for (int m = 0; m < 8; m++) {
        int r = row0 + ty * 8 + m;
        if (r >= NROWS) continue;
        float m0 = (cnt0[r] > 0) ? 1.0f : 0.0f;
        float m1 = (user && g_hist_rb[r] > 0) ? 1.0f : 0.0f;
        F2U c0, c1, c2, c3;
        c0.u = C[m][0]; c1.u = C[m][1]; c2.u = C[m][2]; c3.u = C[m][3];
        float4 olo, ohi;
        olo.x = c0.f.x + blo0.x * m0 + blo1.x * m1;
        olo.y = c0.f.y + blo0.y * m0 + blo1.y * m1;
        olo.z = c1.f.x + blo0.z * m0 + blo1.z * m1;
        olo.w = c1.f.y + blo0.w * m0 + blo1.w * m1;
        ohi.x = c2.f.x + bhi0.x * m0 + bhi1.x * m1;
        ohi.y = c2.f.y + bhi0.y * m0 + bhi1.y * m1;
        ohi.z = c3.f.x + bhi0.z * m0 + bhi1.z * m1;
        ohi.w = c3.f.y + bhi0.w * m0 + bhi1.w * m1;
        *reinterpret_cast<float4*>(out + (size_t)r * D + tx * 4) = olo;
        *reinterpret_cast<float4*>(out + (size_t)r * D + 64 + tx * 4) = ohi;
    }
}

// ---------------- launch ------------------------------------------------------
extern "C" void kernel_launch(void* const* d_in, const int* in_sizes, int n_in,
                              void* d_out, int out_size)
{
    const float* feat_user = (const float*)d_in[0];
    const float* feat_item = (const float*)d_in[1];
    const float* W_f  = (const float*)d_in[2];
    const float* b_f  = (const float*)d_in[3];
    const float* W_r  = (const float*)d_in[4];
    const float* b_r  = (const float*)d_in[5];
    const float* W_rb = (const float*)d_in[6];
    const float* b_rb = (const float*)d_in[7];
    const int* src_f  = (const int*)d_in[8];
    const int* dst_f  = (const int*)d_in[9];
    const int* src_r  = (const int*)d_in[10];
    const int* dst_r  = (const int*)d_in[11];
    const int* src_rb = (const int*)d_in[12];
    const int* dst_rb = (const int*)d_in[13];
    const int E_f  = in_sizes[8];
    const int E_rb = in_sizes[12];
    const int E_r  = in_sizes[10];

    float* out_user = (float*)d_out;
    float* out_item = (float*)d_out + (size_t)NU * D;

    int Emax = E_f > E_rb ? E_f : E_rb;
    if (E_r > Emax) Emax = E_r;

    zero_hist_kernel<<<(NU + 255) / 256, 256>>>();

    {
        dim3 g((Emax + 255) / 256, 3);
        hist3_kernel<<<g, 256>>>(dst_f, dst_rb, dst_r, E_f, E_rb, E_r);
    }

    scan_kernel<<<3, 1024>>>(NU);

    {
        dim3 g((Emax + 255) / 256, 3);
        permute3_kernel<<<g, 256>>>(src_f, dst_f, src_rb, dst_rb, src_r, dst_r,
                                    E_f, E_rb, E_r);
    }

    {
        dim3 g((HALF * 32 + 255) / 256, 3);
        gather3_kernel<<<g, 256>>>((const float4*)feat_user,
                                   (const float4*)feat_item);
    }

    {
        dim3 g((NROWS + 127) / 128, 2);
        gemm_big<<<g, 256>>>(out_user, out_item,
                             W_f, b_f, W_rb, b_rb, W_r, b_r);
    }
}

// round 8
// speedup vs baseline: 1.6255x; 1.1900x over previous
#include <cuda_runtime.h>
#include <cstdint>

#define NU 100000
#define NI 100000
#define D  128
#define EMAX 810000
#define NROWS 100000

typedef unsigned long long u64;

// ---------------- scratch ----------------------------------------------------
__device__ float g_acc_f [(size_t)NU * D];
__device__ float g_acc_rb[(size_t)NU * D];
__device__ float g_acc_r [(size_t)NI * D];
__device__ int   g_hist_f [NU];
__device__ int   g_hist_rb[NU];
__device__ int   g_hist_r [NI];
__device__ int   g_ptr_f [NU + 1];
__device__ int   g_ptr_rb[NU + 1];
__device__ int   g_ptr_r [NI + 1];
__device__ int   g_cur_f [NU];
__device__ int   g_cur_rb[NU];
__device__ int   g_cur_r [NI];
__device__ int   g_srcl_f [EMAX];
__device__ int   g_srcl_rb[EMAX];
__device__ int   g_srcl_r [EMAX];

// ---------------- zero histograms --------------------------------------------
__global__ void zero_hist_kernel() {
    int i = blockIdx.x * blockDim.x + threadIdx.x;
    if (i < NU) { g_hist_f[i] = 0; g_hist_rb[i] = 0; g_hist_r[i] = 0; }
}

// ---------------- fused histogram ---------------------------------------------
__global__ __launch_bounds__(256) void hist3_kernel(
    const int* __restrict__ d0, const int* __restrict__ d1,
    const int* __restrict__ d2, int E0, int E1, int E2)
{
    int et = blockIdx.y;
    const int* dst = (et == 0) ? d0 : (et == 1) ? d1 : d2;
    int* hist = (et == 0) ? g_hist_f : (et == 1) ? g_hist_rb : g_hist_r;
    int E = (et == 0) ? E0 : (et == 1) ? E1 : E2;
    int i = blockIdx.x * blockDim.x + threadIdx.x;
    if (i < E) atomicAdd(&hist[dst[i]], 1);
}

// ---------------- per-etype exclusive scan ------------------------------------
__global__ __launch_bounds__(1024) void scan_kernel(int n)
{
    const int* hist; int* ptr; int* cur;
    if      (blockIdx.x == 0) { hist = g_hist_f;  ptr = g_ptr_f;  cur = g_cur_f;  }
    else if (blockIdx.x == 1) { hist = g_hist_rb; ptr = g_ptr_rb; cur = g_cur_rb; }
    else                      { hist = g_hist_r;  ptr = g_ptr_r;  cur = g_cur_r;  }

    const int T = 1024;
    int chunk = (n + T - 1) / T;
    int lo = threadIdx.x * chunk;
    int hi = lo + chunk; if (hi > n) hi = n;
    if (lo > n) lo = n;

    int s = 0;
    for (int i = lo; i < hi; i++) s += hist[i];

    __shared__ int warpsum[32];
    int lane = threadIdx.x & 31, wid = threadIdx.x >> 5;
    int incl = s;
#pragma unroll
    for (int off = 1; off < 32; off <<= 1) {
        int t = __shfl_up_sync(0xffffffffu, incl, off);
        if (lane >= off) incl += t;
    }
    if (lane == 31) warpsum[wid] = incl;
    __syncthreads();
    if (wid == 0) {
        int w = warpsum[lane];
#pragma unroll
        for (int off = 1; off < 32; off <<= 1) {
            int t = __shfl_up_sync(0xffffffffu, w, off);
            if (lane >= off) w += t;
        }
        warpsum[lane] = w;
    }
    __syncthreads();
    int excl = incl - s + (wid ? warpsum[wid - 1] : 0);
    for (int i = lo; i < hi; i++) {
        ptr[i] = excl; cur[i] = excl; excl += hist[i];
    }
    if (threadIdx.x == 0) ptr[n] = warpsum[31];
}

// ---------------- fused permute -----------------------------------------------
__global__ __launch_bounds__(256) void permute3_kernel(
    const int* __restrict__ s0, const int* __restrict__ d0,
    const int* __restrict__ s1, const int* __restrict__ d1,
    const int* __restrict__ s2, const int* __restrict__ d2,
    int E0, int E1, int E2)
{
    int et = blockIdx.y;
    const int* src = (et == 0) ? s0 : (et == 1) ? s1 : s2;
    const int* dst = (et == 0) ? d0 : (et == 1) ? d1 : d2;
    int* cur = (et == 0) ? g_cur_f : (et == 1) ? g_cur_rb : g_cur_r;
    int* srclist = (et == 0) ? g_srcl_f : (et == 1) ? g_srcl_rb : g_srcl_r;
    int E = (et == 0) ? E0 : (et == 1) ? E1 : E2;
    int i = blockIdx.x * blockDim.x + threadIdx.x;
    if (i < E) {
        int d = dst[i];
        int p = atomicAdd(&cur[d], 1);
        srclist[p] = src[i];
    }
}

// ---------------- fused gather (exact R5 form: one warp per node) -------------
__global__ __launch_bounds__(256) void gather3_kernel(
    const float4* __restrict__ feat_u, const float4* __restrict__ feat_i)
{
    int et = blockIdx.y;
    const float4* feat = (et == 1) ? feat_i : feat_u;
    const int* ptr = (et == 0) ? g_ptr_f : (et == 1) ? g_ptr_rb : g_ptr_r;
    const int* srclist = (et == 0) ? g_srcl_f : (et == 1) ? g_srcl_rb : g_srcl_r;
    float4* acc = (float4*)((et == 0) ? g_acc_f : (et == 1) ? g_acc_rb : g_acc_r);

    int node = (blockIdx.x * 256 + threadIdx.x) >> 5;
    int lane = threadIdx.x & 31;
    if (node >= NROWS) return;
    int beg = __ldg(&ptr[node]);
    int end = __ldg(&ptr[node + 1]);
    int deg = end - beg;

    float4 s = make_float4(0.f, 0.f, 0.f, 0.f);
    int e = beg;
    for (; e + 8 <= end; e += 8) {
        int si[8];
#pragma unroll
        for (int j = 0; j < 8; j++) si[j] = __ldg(&srclist[e + j]);
        float4 v[8];
#pragma unroll
        for (int j = 0; j < 8; j++) v[j] = feat[(size_t)si[j] * 32 + lane];
#pragma unroll
        for (int j = 0; j < 8; j++) {
            s.x += v[j].x; s.y += v[j].y; s.z += v[j].z; s.w += v[j].w;
        }
    }
    for (; e + 4 <= end; e += 4) {
        int si[4];
#pragma unroll
        for (int j = 0; j < 4; j++) si[j] = __ldg(&srclist[e + j]);
        float4 v[4];
#pragma unroll
        for (int j = 0; j < 4; j++) v[j] = feat[(size_t)si[j] * 32 + lane];
#pragma unroll
        for (int j = 0; j < 4; j++) {
            s.x += v[j].x; s.y += v[j].y; s.z += v[j].z; s.w += v[j].w;
        }
    }
    for (; e < end; e++) {
        float4 v = feat[(size_t)__ldg(&srclist[e]) * 32 + lane];
        s.x += v.x; s.y += v.y; s.z += v.z; s.w += v.w;
    }
    float inv = __fdividef(1.0f, (float)(deg > 0 ? deg : 1));
    s.x *= inv; s.y *= inv; s.z *= inv; s.w *= inv;
    acc[(size_t)node * 32 + lane] = s;
}

// ---------------- packed fp32x2 helpers --------------------------------------
__device__ __forceinline__ u64 ffma2(u64 a, u64 b, u64 c) {
    u64 d;
    asm("fma.rn.f32x2 %0, %1, %2, %3;" : "=l"(d) : "l"(a), "l"(b), "l"(c));
    return d;
}
__device__ __forceinline__ u64 dup2(float x) {
    u64 r;
    asm("mov.b64 %0, {%1, %1};" : "=l"(r) : "f"(x));
    return r;
}
union F2U { u64 u; float2 f; };

// ---------------- GEMM: BM=128, BN=128, BK=16, double-buffered ----------------
#define ASTRIDE 132

__global__ __launch_bounds__(256, 2) void gemm_big(
    float* __restrict__ out_user, float* __restrict__ out_item,
    const float* __restrict__ W_f, const float* __restrict__ b_f,
    const float* __restrict__ W_rb, const float* __restrict__ b_rb,
    const float* __restrict__ W_r, const float* __restrict__ b_r)
{
    __shared__ __align__(16) float As[2][16][ASTRIDE];
    __shared__ __align__(16) float Ws[2][16][128];

    const int tid = threadIdx.x;
    const int tx = tid & 15;
    const int ty = tid >> 4;
    const int row0 = blockIdx.x * 128;
    const bool user = (blockIdx.y == 0);
    const int nkt = user ? 16 : 8;
    float* out = user ? out_user : out_item;

    const int a_row = tid >> 1;
    const int a_k   = (tid & 1) * 8;
    const int garow = row0 + a_row;
    const int w_n = tid & 127;
    const int w_k = (tid >> 7) * 8;
    const bool arow_ok = (garow < NROWS);

    u64 C[8][4];
#pragma unroll
    for (int m = 0; m < 8; m++)
#pragma unroll
        for (int c = 0; c < 4; c++) C[m][c] = 0ull;

    float4 a0, a1, w0, w1;

    // ---- global tile load for k-tile kt -> registers
#define LOAD_TILE(kt)                                                           \
    {                                                                           \
        const int seg_ = (kt) >> 3;                                             \
        const int kc_ = ((kt) & 7) * 16;                                        \
        const float* acc_ = user ? (seg_ ? g_acc_rb : g_acc_f) : g_acc_r;       \
        const float* W_ = user ? (seg_ ? W_rb : W_f) : W_r;                     \
        if (arow_ok) {                                                          \
            a0 = *reinterpret_cast<const float4*>(acc_ + (size_t)garow * D + kc_ + a_k);      \
            a1 = *reinterpret_cast<const float4*>(acc_ + (size_t)garow * D + kc_ + a_k + 4);  \
        } else {                                                                \
            a0 = make_float4(0.f, 0.f, 0.f, 0.f); a1 = a0;                      \
        }                                                                       \
        w0 = *reinterpret_cast<const float4*>(W_ + (size_t)w_n * D + kc_ + w_k);     \
        w1 = *reinterpret_cast<const float4*>(W_ + (size_t)w_n * D + kc_ + w_k + 4); \
    }

    // ---- store staged registers into smem buffer b
#define STORE_TILE(b)                                                           \
    {                                                                           \
        As[b][a_k + 0][a_row] = a0.x; As[b][a_k + 1][a_row] = a0.y;             \
        As[b][a_k + 2][a_row] = a0.z; As[b][a_k + 3][a_row] = a0.w;             \
        As[b][a_k + 4][a_row] = a1.x; As[b][a_k + 5][a_row] = a1.y;             \
        As[b][a_k + 6][a_row] = a1.z; As[b][a_k + 7][a_row] = a1.w;             \
        Ws[b][w_k + 0][w_n] = w0.x; Ws[b][w_k + 1][w_n] = w0.y;                 \
        Ws[b][w_k + 2][w_n] = w0.z; Ws[b][w_k + 3][w_n] = w0.w;                 \
        Ws[b][w_k + 4][w_n] = w1.x; Ws[b][w_k + 5][w_n] = w1.y;                 \
        Ws[b][w_k + 6][w_n] = w1.z; Ws[b][w_k + 7][w_n] = w1.w;                 \
    }

    // prologue: fill buffer 0
    LOAD_TILE(0);
    STORE_TILE(0);
    __syncthreads();

    for (int kt = 0; kt < nkt; kt++) {
        const int cb = kt & 1;
        const bool more = (kt + 1 < nkt);
        if (more) LOAD_TILE(kt + 1);

#pragma unroll
        for (int k = 0; k < 16; k++) {
            float4 ar0 = *reinterpret_cast<const float4*>(&As[cb][k][ty * 8]);
            float4 ar1 = *reinterpret_cast<const float4*>(&As[cb][k][ty * 8 + 4]);
            ulonglong2 wlo = *reinterpret_cast<const ulonglong2*>(&Ws[cb][k][tx * 4]);
            ulonglong2 whi = *reinterpret_cast<const ulonglong2*>(&Ws[cb][k][64 + tx * 4]);
            u64 ad[8];
            ad[0] = dup2(ar0.x); ad[1] = dup2(ar0.y);
            ad[2] = dup2(ar0.z); ad[3] = dup2(ar0.w);
            ad[4] = dup2(ar1.x); ad[5] = dup2(ar1.y);
            ad[6] = dup2(ar1.z); ad[7] = dup2(ar1.w);
#pragma unroll
            for (int m = 0; m < 8; m++) {
                C[m][0] = ffma2(ad[m], wlo.x, C[m][0]);
                C[m][1] = ffma2(ad[m], wlo.y, C[m][1]);
                C[m][2] = ffma2(ad[m], whi.x, C[m][2]);
                C[m][3] = ffma2(ad[m], whi.y, C[m][3]);
            }
        }

        if (more) {
            STORE_TILE(cb ^ 1);
            __syncthreads();
        }
    }

    // epilogue
    const float* bias0 = user ? b_f : b_r;
    const int* cnt0 = user ? g_hist_f : g_hist_r;
    float4 blo0 = *reinterpret_cast<const float4*>(bias0 + tx * 4);
    float4 bhi0 = *reinterpret_cast<const float4*>(bias0 + 64 + tx * 4);
    float4 blo1 = make_float4(0.f, 0.f, 0.f, 0.f), bhi1 = blo1;
    if (user) {
        blo1 = *reinterpret_cast<const float4*>(b_rb + tx * 4);
        bhi1 = *reinterpret_cast<const float4*>(b_rb + 64 + tx * 4);
    }
#pragma unroll
    for (int m = 0; m < 8; m++) {
        int r = row0 + ty * 8 + m;
        if (r >= NROWS) continue;
        float m0 = (cnt0[r] > 0) ? 1.0f : 0.0f;
        float m1 = (user && g_hist_rb[r] > 0) ? 1.0f : 0.0f;
        F2U c0, c1, c2, c3;
        c0.u = C[m][0]; c1.u = C[m][1]; c2.u = C[m][2]; c3.u = C[m][3];
        float4 olo, ohi;
        olo.x = c0.f.x + blo0.x * m0 + blo1.x * m1;
        olo.y = c0.f.y + blo0.y * m0 + blo1.y * m1;
        olo.z = c1.f.x + blo0.z * m0 + blo1.z * m1;
        olo.w = c1.f.y + blo0.w * m0 + blo1.w * m1;
        ohi.x = c2.f.x + bhi0.x * m0 + bhi1.x * m1;
        ohi.y = c2.f.y + bhi0.y * m0 + bhi1.y * m1;
        ohi.z = c3.f.x + bhi0.z * m0 + bhi1.z * m1;
        ohi.w = c3.f.y + bhi0.w * m0 + bhi1.w * m1;
        *reinterpret_cast<float4*>(out + (size_t)r * D + tx * 4) = olo;
        *reinterpret_cast<float4*>(out + (size_t)r * D + 64 + tx * 4) = ohi;
    }
}

// ---------------- launch ------------------------------------------------------
extern "C" void kernel_launch(void* const* d_in, const int* in_sizes, int n_in,
                              void* d_out, int out_size)
{
    const float* feat_user = (const float*)d_in[0];
    const float* feat_item = (const float*)d_in[1];
    const float* W_f  = (const float*)d_in[2];
    const float* b_f  = (const float*)d_in[3];
    const float* W_r  = (const float*)d_in[4];
    const float* b_r  = (const float*)d_in[5];
    const float* W_rb = (const float*)d_in[6];
    const float* b_rb = (const float*)d_in[7];
    const int* src_f  = (const int*)d_in[8];
    const int* dst_f  = (const int*)d_in[9];
    const int* src_r  = (const int*)d_in[10];
    const int* dst_r  = (const int*)d_in[11];
    const int* src_rb = (const int*)d_in[12];
    const int* dst_rb = (const int*)d_in[13];
    const int E_f  = in_sizes[8];
    const int E_rb = in_sizes[12];
    const int E_r  = in_sizes[10];

    float* out_user = (float*)d_out;
    float* out_item = (float*)d_out + (size_t)NU * D;

    int Emax = E_f > E_rb ? E_f : E_rb;
    if (E_r > Emax) Emax = E_r;

    zero_hist_kernel<<<(NU + 255) / 256, 256>>>();

    {
        dim3 g((Emax + 255) / 256, 3);
        hist3_kernel<<<g, 256>>>(dst_f, dst_rb, dst_r, E_f, E_rb, E_r);
    }

    scan_kernel<<<3, 1024>>>(NU);

    {
        dim3 g((Emax + 255) / 256, 3);
        permute3_kernel<<<g, 256>>>(src_f, dst_f, src_rb, dst_rb, src_r, dst_r,
                                    E_f, E_rb, E_r);
    }

    {
        dim3 g((NROWS * 32 + 255) / 256, 3);
        gather3_kernel<<<g, 256>>>((const float4*)feat_user,
                                   (const float4*)feat_item);
    }

    {
        dim3 g((NROWS + 127) / 128, 2);
        gemm_big<<<g, 256>>>(out_user, out_item,
                             W_f, b_f, W_rb, b_rb, W_r, b_r);
    }
}

// round 9
// speedup vs baseline: 1.6315x; 1.0037x over previous
#include <cuda_runtime.h>
#include <cstdint>

#define NU 100000
#define NI 100000
#define D  128
#define EMAX 810000
#define NROWS 100000

typedef unsigned long long u64;

// ---------------- scratch ----------------------------------------------------
__device__ float g_acc_f [(size_t)NU * D];
__device__ float g_acc_rb[(size_t)NU * D];
__device__ float g_acc_r [(size_t)NI * D];
__device__ int   g_hist_f [NU];
__device__ int   g_hist_rb[NU];
__device__ int   g_hist_r [NI];
__device__ int   g_ptr_f [NU + 1];
__device__ int   g_ptr_rb[NU + 1];
__device__ int   g_ptr_r [NI + 1];
__device__ int   g_cur_f [NU];
__device__ int   g_cur_rb[NU];
__device__ int   g_cur_r [NI];
__device__ int   g_srcl_f [EMAX];
__device__ int   g_srcl_rb[EMAX];
__device__ int   g_srcl_r [EMAX];

// ---------------- zero histograms --------------------------------------------
__global__ void zero_hist_kernel() {
    int i = blockIdx.x * blockDim.x + threadIdx.x;
    if (i < NU) { g_hist_f[i] = 0; g_hist_rb[i] = 0; g_hist_r[i] = 0; }
}

// ---------------- fused histogram ---------------------------------------------
__global__ __launch_bounds__(256) void hist3_kernel(
    const int* __restrict__ d0, const int* __restrict__ d1,
    const int* __restrict__ d2, int E0, int E1, int E2)
{
    int et = blockIdx.y;
    const int* dst = (et == 0) ? d0 : (et == 1) ? d1 : d2;
    int* hist = (et == 0) ? g_hist_f : (et == 1) ? g_hist_rb : g_hist_r;
    int E = (et == 0) ? E0 : (et == 1) ? E1 : E2;
    int i = blockIdx.x * blockDim.x + threadIdx.x;
    if (i < E) atomicAdd(&hist[__ldcs(&dst[i])], 1);
}

// ---------------- per-etype exclusive scan ------------------------------------
__global__ __launch_bounds__(1024) void scan_kernel(int n)
{
    const int* hist; int* ptr; int* cur;
    if      (blockIdx.x == 0) { hist = g_hist_f;  ptr = g_ptr_f;  cur = g_cur_f;  }
    else if (blockIdx.x == 1) { hist = g_hist_rb; ptr = g_ptr_rb; cur = g_cur_rb; }
    else                      { hist = g_hist_r;  ptr = g_ptr_r;  cur = g_cur_r;  }

    const int T = 1024;
    int chunk = (n + T - 1) / T;
    int lo = threadIdx.x * chunk;
    int hi = lo + chunk; if (hi > n) hi = n;
    if (lo > n) lo = n;

    int s = 0;
    for (int i = lo; i < hi; i++) s += hist[i];

    __shared__ int warpsum[32];
    int lane = threadIdx.x & 31, wid = threadIdx.x >> 5;
    int incl = s;
#pragma unroll
    for (int off = 1; off < 32; off <<= 1) {
        int t = __shfl_up_sync(0xffffffffu, incl, off);
        if (lane >= off) incl += t;
    }
    if (lane == 31) warpsum[wid] = incl;
    __syncthreads();
    if (wid == 0) {
        int w = warpsum[lane];
#pragma unroll
        for (int off = 1; off < 32; off <<= 1) {
            int t = __shfl_up_sync(0xffffffffu, w, off);
            if (lane >= off) w += t;
        }
        warpsum[lane] = w;
    }
    __syncthreads();
    int excl = incl - s + (wid ? warpsum[wid - 1] : 0);
    for (int i = lo; i < hi; i++) {
        ptr[i] = excl; cur[i] = excl; excl += hist[i];
    }
    if (threadIdx.x == 0) ptr[n] = warpsum[31];
}

// ---------------- fused permute -----------------------------------------------
__global__ __launch_bounds__(256) void permute3_kernel(
    const int* __restrict__ s0, const int* __restrict__ d0,
    const int* __restrict__ s1, const int* __restrict__ d1,
    const int* __restrict__ s2, const int* __restrict__ d2,
    int E0, int E1, int E2)
{
    int et = blockIdx.y;
    const int* src = (et == 0) ? s0 : (et == 1) ? s1 : s2;
    const int* dst = (et == 0) ? d0 : (et == 1) ? d1 : d2;
    int* cur = (et == 0) ? g_cur_f : (et == 1) ? g_cur_rb : g_cur_r;
    int* srclist = (et == 0) ? g_srcl_f : (et == 1) ? g_srcl_rb : g_srcl_r;
    int E = (et == 0) ? E0 : (et == 1) ? E1 : E2;
    int i = blockIdx.x * blockDim.x + threadIdx.x;
    if (i < E) {
        int d = __ldcs(&dst[i]);
        int v = __ldcs(&src[i]);
        int p = atomicAdd(&cur[d], 1);
        __stcs(&srclist[p], v);
    }
}

// ---------------- fused gather (R5 form + streaming hints) --------------------
__global__ __launch_bounds__(256) void gather3_kernel(
    const float4* __restrict__ feat_u, const float4* __restrict__ feat_i)
{
    int et = blockIdx.y;
    const float4* feat = (et == 1) ? feat_i : feat_u;
    const int* ptr = (et == 0) ? g_ptr_f : (et == 1) ? g_ptr_rb : g_ptr_r;
    const int* srclist = (et == 0) ? g_srcl_f : (et == 1) ? g_srcl_rb : g_srcl_r;
    float4* acc = (float4*)((et == 0) ? g_acc_f : (et == 1) ? g_acc_rb : g_acc_r);

    int node = (blockIdx.x * 256 + threadIdx.x) >> 5;
    int lane = threadIdx.x & 31;
    if (node >= NROWS) return;
    int beg = __ldg(&ptr[node]);
    int end = __ldg(&ptr[node + 1]);
    int deg = end - beg;

    float4 s = make_float4(0.f, 0.f, 0.f, 0.f);
    int e = beg;
    for (; e + 8 <= end; e += 8) {
        int si[8];
#pragma unroll
        for (int j = 0; j < 8; j++) si[j] = __ldcs(&srclist[e + j]);
        float4 v[8];
#pragma unroll
        for (int j = 0; j < 8; j++) v[j] = __ldg(&feat[(size_t)si[j] * 32 + lane]);
#pragma unroll
        for (int j = 0; j < 8; j++) {
            s.x += v[j].x; s.y += v[j].y; s.z += v[j].z; s.w += v[j].w;
        }
    }
    for (; e + 4 <= end; e += 4) {
        int si[4];
#pragma unroll
        for (int j = 0; j < 4; j++) si[j] = __ldcs(&srclist[e + j]);
        float4 v[4];
#pragma unroll
        for (int j = 0; j < 4; j++) v[j] = __ldg(&feat[(size_t)si[j] * 32 + lane]);
#pragma unroll
        for (int j = 0; j < 4; j++) {
            s.x += v[j].x; s.y += v[j].y; s.z += v[j].z; s.w += v[j].w;
        }
    }
    for (; e < end; e++) {
        float4 v = __ldg(&feat[(size_t)__ldcs(&srclist[e]) * 32 + lane]);
        s.x += v.x; s.y += v.y; s.z += v.z; s.w += v.w;
    }
    float inv = __fdividef(1.0f, (float)(deg > 0 ? deg : 1));
    s.x *= inv; s.y *= inv; s.z *= inv; s.w *= inv;
    __stcs(&acc[(size_t)node * 32 + lane], s);
}

// ---------------- packed fp32x2 helpers --------------------------------------
__device__ __forceinline__ u64 ffma2(u64 a, u64 b, u64 c) {
    u64 d;
    asm("fma.rn.f32x2 %0, %1, %2, %3;" : "=l"(d) : "l"(a), "l"(b), "l"(c));
    return d;
}
__device__ __forceinline__ u64 dup2(float x) {
    u64 r;
    asm("mov.b64 %0, {%1, %1};" : "=l"(r) : "f"(x));
    return r;
}
union F2U { u64 u; float2 f; };

// ---------------- GEMM: BM=128, BN=128, BK=16 (R5 form + streaming hints) -----
#define ASTRIDE 132

__global__ __launch_bounds__(256, 2) void gemm_big(
    float* __restrict__ out_user, float* __restrict__ out_item,
    const float* __restrict__ W_f, const float* __restrict__ b_f,
    const float* __restrict__ W_rb, const float* __restrict__ b_rb,
    const float* __restrict__ W_r, const float* __restrict__ b_r)
{
    __shared__ __align__(16) float As[16][ASTRIDE];
    __shared__ __align__(16) float Ws[16][128];

    const int tid = threadIdx.x;
    const int tx = tid & 15;
    const int ty = tid >> 4;
    const int row0 = blockIdx.x * 128;
    const bool user = (blockIdx.y == 0);
    const int nkt = user ? 16 : 8;
    float* out = user ? out_user : out_item;

    const int a_row = tid >> 1;
    const int a_k   = (tid & 1) * 8;
    const int garow = row0 + a_row;
    const int w_n = tid & 127;
    const int w_k = (tid >> 7) * 8;

    u64 C[8][4];
#pragma unroll
    for (int m = 0; m < 8; m++)
#pragma unroll
        for (int c = 0; c < 4; c++) C[m][c] = 0ull;

    for (int kt = 0; kt < nkt; kt++) {
        const int seg = kt >> 3;
        const int kc = (kt & 7) * 16;
        const float* acc = user ? (seg ? g_acc_rb : g_acc_f) : g_acc_r;
        const float* W = user ? (seg ? W_rb : W_f) : W_r;

        float4 a0 = make_float4(0.f, 0.f, 0.f, 0.f), a1 = a0;
        if (garow < NROWS) {
            a0 = __ldcs(reinterpret_cast<const float4*>(acc + (size_t)garow * D + kc + a_k));
            a1 = __ldcs(reinterpret_cast<const float4*>(acc + (size_t)garow * D + kc + a_k + 4));
        }
        float4 w0 = __ldg(reinterpret_cast<const float4*>(W + (size_t)w_n * D + kc + w_k));
        float4 w1 = __ldg(reinterpret_cast<const float4*>(W + (size_t)w_n * D + kc + w_k + 4));

        __syncthreads();
        As[a_k + 0][a_row] = a0.x;
        As[a_k + 1][a_row] = a0.y;
        As[a_k + 2][a_row] = a0.z;
        As[a_k + 3][a_row] = a0.w;
        As[a_k + 4][a_row] = a1.x;
        As[a_k + 5][a_row] = a1.y;
        As[a_k + 6][a_row] = a1.z;
        As[a_k + 7][a_row] = a1.w;
        Ws[w_k + 0][w_n] = w0.x;
        Ws[w_k + 1][w_n] = w0.y;
        Ws[w_k + 2][w_n] = w0.z;
        Ws[w_k + 3][w_n] = w0.w;
        Ws[w_k + 4][w_n] = w1.x;
        Ws[w_k + 5][w_n] = w1.y;
        Ws[w_k + 6][w_n] = w1.z;
        Ws[w_k + 7][w_n] = w1.w;
        __syncthreads();

#pragma unroll
        for (int k = 0; k < 16; k++) {
            float4 ar0 = *reinterpret_cast<const float4*>(&As[k][ty * 8]);
            float4 ar1 = *reinterpret_cast<const float4*>(&As[k][ty * 8 + 4]);
            ulonglong2 wlo = *reinterpret_cast<const ulonglong2*>(&Ws[k][tx * 4]);
            ulonglong2 whi = *reinterpret_cast<const ulonglong2*>(&Ws[k][64 + tx * 4]);
            u64 ad[8];
            ad[0] = dup2(ar0.x); ad[1] = dup2(ar0.y);
            ad[2] = dup2(ar0.z); ad[3] = dup2(ar0.w);
            ad[4] = dup2(ar1.x); ad[5] = dup2(ar1.y);
            ad[6] = dup2(ar1.z); ad[7] = dup2(ar1.w);
#pragma unroll
            for (int m = 0; m < 8; m++) {
                C[m][0] = ffma2(ad[m], wlo.x, C[m][0]);
                C[m][1] = ffma2(ad[m], wlo.y, C[m][1]);
                C[m][2] = ffma2(ad[m], whi.x, C[m][2]);
                C[m][3] = ffma2(ad[m], whi.y, C[m][3]);
            }
        }
    }

    const float* bias0 = user ? b_f : b_r;
    const int* cnt0 = user ? g_hist_f : g_hist_r;
    float4 blo0 = *reinterpret_cast<const float4*>(bias0 + tx * 4);
    float4 bhi0 = *reinterpret_cast<const float4*>(bias0 + 64 + tx * 4);
    float4 blo1 = make_float4(0.f, 0.f, 0.f, 0.f), bhi1 = blo1;
    if (user) {
        blo1 = *reinterpret_cast<const float4*>(b_rb + tx * 4);
        bhi1 = *reinterpret_cast<const float4*>(b_rb + 64 + tx * 4);
    }
#pragma unroll
    for (int m = 0; m < 8; m++) {
        int r = row0 + ty * 8 + m;
        if (r >= NROWS) continue;
        float m0 = (cnt0[r] > 0) ? 1.0f : 0.0f;
        float m1 = (user && g_hist_rb[r] > 0) ? 1.0f : 0.0f;
        F2U c0, c1, c2, c3;
        c0.u = C[m][0]; c1.u = C[m][1]; c2.u = C[m][2]; c3.u = C[m][3];
        float4 olo, ohi;
        olo.x = c0.f.x + blo0.x * m0 + blo1.x * m1;
        olo.y = c0.f.y + blo0.y * m0 + blo1.y * m1;
        olo.z = c1.f.x + blo0.z * m0 + blo1.z * m1;
        olo.w = c1.f.y + blo0.w * m0 + blo1.w * m1;
        ohi.x = c2.f.x + bhi0.x * m0 + bhi1.x * m1;
        ohi.y = c2.f.y + bhi0.y * m0 + bhi1.y * m1;
        ohi.z = c3.f.x + bhi0.z * m0 + bhi1.z * m1;
        ohi.w = c3.f.y + bhi0.w * m0 + bhi1.w * m1;
        __stcs(reinterpret_cast<float4*>(out + (size_t)r * D + tx * 4), olo);
        __stcs(reinterpret_cast<float4*>(out + (size_t)r * D + 64 + tx * 4), ohi);
    }
}

// ---------------- launch ------------------------------------------------------
extern "C" void kernel_launch(void* const* d_in, const int* in_sizes, int n_in,
                              void* d_out, int out_size)
{
    const float* feat_user = (const float*)d_in[0];
    const float* feat_item = (const float*)d_in[1];
    const float* W_f  = (const float*)d_in[2];
    const float* b_f  = (const float*)d_in[3];
    const float* W_r  = (const float*)d_in[4];
    const float* b_r  = (const float*)d_in[5];
    const float* W_rb = (const float*)d_in[6];
    const float* b_rb = (const float*)d_in[7];
    const int* src_f  = (const int*)d_in[8];
    const int* dst_f  = (const int*)d_in[9];
    const int* src_r  = (const int*)d_in[10];
    const int* dst_r  = (const int*)d_in[11];
    const int* src_rb = (const int*)d_in[12];
    const int* dst_rb = (const int*)d_in[13];
    const int E_f  = in_sizes[8];
    const int E_rb = in_sizes[12];
    const int E_r  = in_sizes[10];

    float* out_user = (float*)d_out;
    float* out_item = (float*)d_out + (size_t)NU * D;

    int Emax = E_f > E_rb ? E_f : E_rb;
    if (E_r > Emax) Emax = E_r;

    zero_hist_kernel<<<(NU + 255) / 256, 256>>>();

    {
        dim3 g((Emax + 255) / 256, 3);
        hist3_kernel<<<g, 256>>>(dst_f, dst_rb, dst_r, E_f, E_rb, E_r);
    }

    scan_kernel<<<3, 1024>>>(NU);

    {
        dim3 g((Emax + 255) / 256, 3);
        permute3_kernel<<<g, 256>>>(src_f, dst_f, src_rb, dst_rb, src_r, dst_r,
                                    E_f, E_rb, E_r);
    }

    {
        dim3 g((NROWS * 32 + 255) / 256, 3);
        gather3_kernel<<<g, 256>>>((const float4*)feat_user,
                                   (const float4*)feat_item);
    }

    {
        dim3 g((NROWS + 127) / 128, 2);
        gemm_big<<<g, 256>>>(out_user, out_item,
                             W_f, b_f, W_rb, b_rb, W_r, b_r);
    }
}

// round 11
// speedup vs baseline: 1.8529x; 1.1357x over previous
#include <cuda_runtime.h>
#include <cuda_bf16.h>
#include <cstdint>

#define NU 100000
#define NI 100000
#define D  128
#define EMAX 810000
#define NROWS 100000

typedef __nv_bfloat16 bf16;
typedef unsigned int u32;

// ---------------- scratch ----------------------------------------------------
__device__ bf16 g_ah_f [(size_t)NU * D];
__device__ bf16 g_al_f [(size_t)NU * D];
__device__ bf16 g_ah_rb[(size_t)NU * D];
__device__ bf16 g_al_rb[(size_t)NU * D];
__device__ bf16 g_ah_r [(size_t)NI * D];
__device__ bf16 g_al_r [(size_t)NI * D];
__device__ bf16 g_wh[3 * D * D];
__device__ bf16 g_wl[3 * D * D];
__device__ int  g_hist_f [NU];
__device__ int  g_hist_rb[NU];
__device__ int  g_hist_r [NI];
__device__ int  g_ptr_f [NU + 1];
__device__ int  g_ptr_rb[NU + 1];
__device__ int  g_ptr_r [NI + 1];
__device__ int  g_cur_f [NU];
__device__ int  g_cur_rb[NU];
__device__ int  g_cur_r [NI];
__device__ int  g_srcl_f [EMAX];
__device__ int  g_srcl_rb[EMAX];
__device__ int  g_srcl_r [EMAX];

// ---------------- zero histograms --------------------------------------------
__global__ void zero_hist_kernel() {
    int i = blockIdx.x * blockDim.x + threadIdx.x;
    if (i < NU) { g_hist_f[i] = 0; g_hist_rb[i] = 0; g_hist_r[i] = 0; }
}

// ---------------- fused histogram ---------------------------------------------
__global__ __launch_bounds__(256) void hist3_kernel(
    const int* __restrict__ d0, const int* __restrict__ d1,
    const int* __restrict__ d2, int E0, int E1, int E2)
{
    int et = blockIdx.y;
    const int* dst = (et == 0) ? d0 : (et == 1) ? d1 : d2;
    int* hist = (et == 0) ? g_hist_f : (et == 1) ? g_hist_rb : g_hist_r;
    int E = (et == 0) ? E0 : (et == 1) ? E1 : E2;
    int i = blockIdx.x * blockDim.x + threadIdx.x;
    if (i < E) atomicAdd(&hist[dst[i]], 1);
}

// ---------------- per-etype exclusive scan ------------------------------------
__global__ __launch_bounds__(1024) void scan_kernel(int n)
{
    const int* hist; int* ptr; int* cur;
    if      (blockIdx.x == 0) { hist = g_hist_f;  ptr = g_ptr_f;  cur = g_cur_f;  }
    else if (blockIdx.x == 1) { hist = g_hist_rb; ptr = g_ptr_rb; cur = g_cur_rb; }
    else                      { hist = g_hist_r;  ptr = g_ptr_r;  cur = g_cur_r;  }

    const int T = 1024;
    int chunk = (n + T - 1) / T;
    int lo = threadIdx.x * chunk;
    int hi = lo + chunk; if (hi > n) hi = n;
    if (lo > n) lo = n;

    int s = 0;
    for (int i = lo; i < hi; i++) s += hist[i];

    __shared__ int warpsum[32];
    int lane = threadIdx.x & 31, wid = threadIdx.x >> 5;
    int incl = s;
#pragma unroll
    for (int off = 1; off < 32; off <<= 1) {
        int t = __shfl_up_sync(0xffffffffu, incl, off);
        if (lane >= off) incl += t;
    }
    if (lane == 31) warpsum[wid] = incl;
    __syncthreads();
    if (wid == 0) {
        int w = warpsum[lane];
#pragma unroll
        for (int off = 1; off < 32; off <<= 1) {
            int t = __shfl_up_sync(0xffffffffu, w, off);
            if (lane >= off) w += t;
        }
        warpsum[lane] = w;
    }
    __syncthreads();
    int excl = incl - s + (wid ? warpsum[wid - 1] : 0);
    for (int i = lo; i < hi; i++) {
        ptr[i] = excl; cur[i] = excl; excl += hist[i];
    }
    if (threadIdx.x == 0) ptr[n] = warpsum[31];
}

// ---------------- fused permute -----------------------------------------------
__global__ __launch_bounds__(256) void permute3_kernel(
    const int* __restrict__ s0, const int* __restrict__ d0,
    const int* __restrict__ s1, const int* __restrict__ d1,
    const int* __restrict__ s2, const int* __restrict__ d2,
    int E0, int E1, int E2)
{
    int et = blockIdx.y;
    const int* src = (et == 0) ? s0 : (et == 1) ? s1 : s2;
    const int* dst = (et == 0) ? d0 : (et == 1) ? d1 : d2;
    int* cur = (et == 0) ? g_cur_f : (et == 1) ? g_cur_rb : g_cur_r;
    int* srclist = (et == 0) ? g_srcl_f : (et == 1) ? g_srcl_rb : g_srcl_r;
    int E = (et == 0) ? E0 : (et == 1) ? E1 : E2;
    int i = blockIdx.x * blockDim.x + threadIdx.x;
    if (i < E) {
        int d = dst[i];
        int p = atomicAdd(&cur[d], 1);
        srclist[p] = src[i];
    }
}

// ---------------- hi/lo bf16 split helpers ------------------------------------
static __device__ __forceinline__ void split_pack(float a, float b, u32& hi, u32& lo) {
    bf16 ha = __float2bfloat16_rn(a);
    bf16 hb = __float2bfloat16_rn(b);
    bf16 la = __float2bfloat16_rn(a - __bfloat162float(ha));
    bf16 lb = __float2bfloat16_rn(b - __bfloat162float(hb));
    hi = (u32)__bfloat16_as_ushort(ha) | ((u32)__bfloat16_as_ushort(hb) << 16);
    lo = (u32)__bfloat16_as_ushort(la) | ((u32)__bfloat16_as_ushort(lb) << 16);
}

// ---------------- W split prep -------------------------------------------------
__global__ void wprep_kernel(const float* __restrict__ Wf,
                             const float* __restrict__ Wrb,
                             const float* __restrict__ Wr)
{
    int et = blockIdx.x;
    const float* W = (et == 0) ? Wf : (et == 1) ? Wrb : Wr;
    bf16* wh = g_wh + et * D * D;
    bf16* wl = g_wl + et * D * D;
    for (int i = threadIdx.x; i < D * D; i += blockDim.x) {
        float x = W[i];
        bf16 h = __float2bfloat16_rn(x);
        wh[i] = h;
        wl[i] = __float2bfloat16_rn(x - __bfloat162float(h));
    }
}

// ---------------- fused gather (R5 form; writes bf16 hi/lo means) -------------
__global__ __launch_bounds__(256) void gather3_kernel(
    const float4* __restrict__ feat_u, const float4* __restrict__ feat_i)
{
    int et = blockIdx.y;
    const float4* feat = (et == 1) ? feat_i : feat_u;
    const int* ptr = (et == 0) ? g_ptr_f : (et == 1) ? g_ptr_rb : g_ptr_r;
    const int* srclist = (et == 0) ? g_srcl_f : (et == 1) ? g_srcl_rb : g_srcl_r;
    bf16* ah = (et == 0) ? g_ah_f : (et == 1) ? g_ah_rb : g_ah_r;
    bf16* al = (et == 0) ? g_al_f : (et == 1) ? g_al_rb : g_al_r;

    int node = (blockIdx.x * 256 + threadIdx.x) >> 5;
    int lane = threadIdx.x & 31;
    if (node >= NROWS) return;
    int beg = __ldg(&ptr[node]);
    int end = __ldg(&ptr[node + 1]);
    int deg = end - beg;

    float4 s = make_float4(0.f, 0.f, 0.f, 0.f);
    int e = beg;
    for (; e + 8 <= end; e += 8) {
        int si[8];
#pragma unroll
        for (int j = 0; j < 8; j++) si[j] = __ldg(&srclist[e + j]);
        float4 v[8];
#pragma unroll
        for (int j = 0; j < 8; j++) v[j] = feat[(size_t)si[j] * 32 + lane];
#pragma unroll
        for (int j = 0; j < 8; j++) {
            s.x += v[j].x; s.y += v[j].y; s.z += v[j].z; s.w += v[j].w;
        }
    }
    for (; e + 4 <= end; e += 4) {
        int si[4];
#pragma unroll
        for (int j = 0; j < 4; j++) si[j] = __ldg(&srclist[e + j]);
        float4 v[4];
#pragma unroll
        for (int j = 0; j < 4; j++) v[j] = feat[(size_t)si[j] * 32 + lane];
#pragma unroll
        for (int j = 0; j < 4; j++) {
            s.x += v[j].x; s.y += v[j].y; s.z += v[j].z; s.w += v[j].w;
        }
    }
    for (; e < end; e++) {
        float4 v = feat[(size_t)__ldg(&srclist[e]) * 32 + lane];
        s.x += v.x; s.y += v.y; s.z += v.z; s.w += v.w;
    }
    float inv = __fdividef(1.0f, (float)(deg > 0 ? deg : 1));
    s.x *= inv; s.y *= inv; s.z *= inv; s.w *= inv;

    u32 h0, l0, h1, l1;
    split_pack(s.x, s.y, h0, l0);
    split_pack(s.z, s.w, h1, l1);
    uint2 hv = make_uint2(h0, h1);
    uint2 lv = make_uint2(l0, l1);
    *reinterpret_cast<uint2*>(ah + (size_t)node * D + lane * 4) = hv;
    *reinterpret_cast<uint2*>(al + (size_t)node * D + lane * 4) = lv;
}

// ---------------- bf16 mma.sync GEMM ------------------------------------------
// out[r][:] = sum over chunk list (A_chunk @ W_chunk^T) + masked biases.
// A chunks are bf16 [NROWS][128]; W chunks bf16 [128 n][128 k].
// mma.sync m16n8k16 row.col: A row-major (k contig), B col-major (= W[n][k]).
#define ASTR 72   // smem row stride in bf16 (64 data + 8 pad) -> conflict-free frags

static __device__ __forceinline__ void mma_bf16(float* c, const u32* a, u32 b0, u32 b1) {
    asm volatile(
        "mma.sync.aligned.m16n8k16.row.col.f32.bf16.bf16.f32 "
        "{%0,%1,%2,%3}, {%4,%5,%6,%7}, {%8,%9}, {%0,%1,%2,%3};"
        : "+f"(c[0]), "+f"(c[1]), "+f"(c[2]), "+f"(c[3])
        : "r"(a[0]), "r"(a[1]), "r"(a[2]), "r"(a[3]), "r"(b0), "r"(b1));
}

__global__ __launch_bounds__(256, 2) void gemm_mma(
    float* __restrict__ out_user, float* __restrict__ out_item,
    const float* __restrict__ b_f, const float* __restrict__ b_rb,
    const float* __restrict__ b_r)
{
    __shared__ __align__(16) bf16 As[128 * ASTR];
    __shared__ __align__(16) bf16 Bs[128 * ASTR];

    const int tid = threadIdx.x;
    const int wid = tid >> 5, lane = tid & 31;
    const int g = lane >> 2, t = lane & 3;
    const int row0 = blockIdx.x * 128;
    const bool user = (blockIdx.y == 0);

    const int wm0 = (wid >> 1) * 32;   // warp M origin: 0,32,64,96
    const int wn0 = (wid & 1) * 64;    // warp N origin: 0,64

    // chunk list: (A source, W source) pairs, each K=128
    const bf16* APTR[6]; const bf16* WPTR[6];
    int npairs;
    if (user) {
        APTR[0] = g_ah_f;  WPTR[0] = g_wh;
        APTR[1] = g_al_f;  WPTR[1] = g_wh;
        APTR[2] = g_ah_f;  WPTR[2] = g_wl;
        APTR[3] = g_ah_rb; WPTR[3] = g_wh + D * D;
        APTR[4] = g_al_rb; WPTR[4] = g_wh + D * D;
        APTR[5] = g_ah_rb; WPTR[5] = g_wl + D * D;
        npairs = 6;
    } else {
        APTR[0] = g_ah_r;  WPTR[0] = g_wh + 2 * D * D;
        APTR[1] = g_al_r;  WPTR[1] = g_wh + 2 * D * D;
        APTR[2] = g_ah_r;  WPTR[2] = g_wl + 2 * D * D;
        npairs = 3;
    }

    float C[2][8][4];
#pragma unroll
    for (int mt = 0; mt < 2; mt++)
#pragma unroll
        for (int nt = 0; nt < 8; nt++)
#pragma unroll
            for (int q = 0; q < 4; q++) C[mt][nt][q] = 0.f;

    // stage loaders: row = tid>>1 (0..127), 32-bf16 half per thread
    const int lrow = tid >> 1;
    const int lcol = (tid & 1) * 32;
    const bool arow_ok = (row0 + lrow < NROWS);

    for (int p = 0; p < npairs; p++) {
        const bf16* Asrc = APTR[p];
        const bf16* Wsrc = WPTR[p];
#pragma unroll
        for (int st = 0; st < 2; st++) {
            const int kc = st * 64;
            // global loads to regs
            uint4 av[4], wv[4];
            const bf16* as = Asrc + (size_t)(row0 + lrow) * D + kc + lcol;
            const bf16* ws = Wsrc + (size_t)lrow * D + kc + lcol;
#pragma unroll
            for (int q = 0; q < 4; q++) {
                av[q] = arow_ok ? *reinterpret_cast<const uint4*>(as + q * 8)
                                : make_uint4(0u, 0u, 0u, 0u);
                wv[q] = *reinterpret_cast<const uint4*>(ws + q * 8);
            }
            __syncthreads();   // previous stage's mma reads done
#pragma unroll
            for (int q = 0; q < 4; q++) {
                *reinterpret_cast<uint4*>(&As[lrow * ASTR + lcol + q * 8]) = av[q];
                *reinterpret_cast<uint4*>(&Bs[lrow * ASTR + lcol + q * 8]) = wv[q];
            }
            __syncthreads();   // tiles ready

#pragma unroll
            for (int ks = 0; ks < 4; ks++) {
                u32 a[2][4];
#pragma unroll
                for (int mt = 0; mt < 2; mt++) {
                    const bf16* ab = &As[(wm0 + mt * 16 + g) * ASTR + ks * 16 + t * 2];
                    a[mt][0] = *reinterpret_cast<const u32*>(ab);
                    a[mt][1] = *reinterpret_cast<const u32*>(ab + 8 * ASTR);
                    a[mt][2] = *reinterpret_cast<const u32*>(ab + 8);
                    a[mt][3] = *reinterpret_cast<const u32*>(ab + 8 * ASTR + 8);
                }
#pragma unroll
                for (int nt = 0; nt < 8; nt++) {
                    const bf16* bb = &Bs[(wn0 + nt * 8 + g) * ASTR + ks * 16 + t * 2];
                    u32 b0 = *reinterpret_cast<const u32*>(bb);
                    u32 b1 = *reinterpret_cast<const u32*>(bb + 8);
                    mma_bf16(C[0][nt], a[0], b0, b1);
                    mma_bf16(C[1][nt], a[1], b0, b1);
                }
            }
        }
    }

    // epilogue: masked biases, direct stores
    const float* bias0 = user ? b_f : b_r;
    const int* cnt0 = user ? g_hist_f : g_hist_r;
    float* out = user ? out_user : out_item;
#pragma unroll
    for (int mt = 0; mt < 2; mt++) {
        int r0 = row0 + wm0 + mt * 16 + g;
        int r1 = r0 + 8;
        bool ok0 = (r0 < NROWS), ok1 = (r1 < NROWS);
        float m00 = (ok0 && cnt0[ok0 ? r0 : 0] > 0) ? 1.f : 0.f;
        float m01 = (ok1 && cnt0[ok1 ? r1 : 0] > 0) ? 1.f : 0.f;
        float m10 = (user && ok0 && g_hist_rb[ok0 ? r0 : 0] > 0) ? 1.f : 0.f;
        float m11 = (user && ok1 && g_hist_rb[ok1 ? r1 : 0] > 0) ? 1.f : 0.f;
#pragma unroll
        for (int nt = 0; nt < 8; nt++) {
            int col = wn0 + nt * 8 + t * 2;
            float bb0 = bias0[col], bb1 = bias0[col + 1];
            float br0 = user ? b_rb[col] : 0.f;
            float br1 = user ? b_rb[col + 1] : 0.f;
            if (ok0) {
                float2 v;
                v.x = C[mt][nt][0] + bb0 * m00 + br0 * m10;
                v.y = C[mt][nt][1] + bb1 * m00 + br1 * m10;
                *reinterpret_cast<float2*>(out + (size_t)r0 * D + col) = v;
            }
            if (ok1) {
                float2 v;
                v.x = C[mt][nt][2] + bb0 * m01 + br0 * m11;
                v.y = C[mt][nt][3] + bb1 * m01 + br1 * m11;
                *reinterpret_cast<float2*>(out + (size_t)r1 * D + col) = v;
            }
        }
    }
}

// ---------------- launch ------------------------------------------------------
extern "C" void kernel_launch(void* const* d_in, const int* in_sizes, int n_in,
                              void* d_out, int out_size)
{
    const float* feat_user = (const float*)d_in[0];
    const float* feat_item = (const float*)d_in[1];
    const float* W_f  = (const float*)d_in[2];
    const float* b_f  = (const float*)d_in[3];
    const float* W_r  = (const float*)d_in[4];
    const float* b_r  = (const float*)d_in[5];
    const float* W_rb = (const float*)d_in[6];
    const float* b_rb = (const float*)d_in[7];
    const int* src_f  = (const int*)d_in[8];
    const int* dst_f  = (const int*)d_in[9];
    const int* src_r  = (const int*)d_in[10];
    const int* dst_r  = (const int*)d_in[11];
    const int* src_rb = (const int*)d_in[12];
    const int* dst_rb = (const int*)d_in[13];
    const int E_f  = in_sizes[8];
    const int E_rb = in_sizes[12];
    const int E_r  = in_sizes[10];

    float* out_user = (float*)d_out;
    float* out_item = (float*)d_out + (size_t)NU * D;

    int Emax = E_f > E_rb ? E_f : E_rb;
    if (E_r > Emax) Emax = E_r;

    zero_hist_kernel<<<(NU + 255) / 256, 256>>>();

    {
        dim3 g((Emax + 255) / 256, 3);
        hist3_kernel<<<g, 256>>>(dst_f, dst_rb, dst_r, E_f, E_rb, E_r);
    }

    wprep_kernel<<<3, 256>>>(W_f, W_rb, W_r);

    scan_kernel<<<3, 1024>>>(NU);

    {
        dim3 g((Emax + 255) / 256, 3);
        permute3_kernel<<<g, 256>>>(src_f, dst_f, src_rb, dst_rb, src_r, dst_r,
                                    E_f, E_rb, E_r);
    }

    {
        dim3 g((NROWS * 32 + 255) / 256, 3);
        gather3_kernel<<<g, 256>>>((const float4*)feat_user,
                                   (const float4*)feat_item);
    }

    {
        dim3 g((NROWS + 127) / 128, 2);
        gemm_mma<<<g, 256>>>(out_user, out_item, b_f, b_rb, b_r);
    }
}

// round 12
// speedup vs baseline: 2.6985x; 1.4563x over previous
#include <cuda_runtime.h>
#include <cuda_bf16.h>
#include <cstdint>

#define NU 100000
#define NI 100000
#define D  128
#define EMAX 810000
#define NROWS 100000
#define SCAN_NB ((NROWS + 1023) / 1024)   // 98 blocks of 1024 elements

typedef __nv_bfloat16 bf16;
typedef unsigned int u32;

// ---------------- scratch ----------------------------------------------------
__device__ bf16 g_ah_f [(size_t)NU * D];
__device__ bf16 g_al_f [(size_t)NU * D];
__device__ bf16 g_ah_rb[(size_t)NU * D];
__device__ bf16 g_al_rb[(size_t)NU * D];
__device__ bf16 g_ah_r [(size_t)NI * D];
__device__ bf16 g_al_r [(size_t)NI * D];
__device__ bf16 g_wh[3 * D * D];
__device__ bf16 g_wl[3 * D * D];
__device__ int  g_hist_f [NU];
__device__ int  g_hist_rb[NU];
__device__ int  g_hist_r [NI];
__device__ int  g_ptr_f [NU + 1];
__device__ int  g_ptr_rb[NU + 1];
__device__ int  g_ptr_r [NI + 1];
__device__ int  g_cur_f [NU];
__device__ int  g_cur_rb[NU];
__device__ int  g_cur_r [NI];
__device__ int  g_srcl_f [EMAX];
__device__ int  g_srcl_rb[EMAX];
__device__ int  g_srcl_r [EMAX];
__device__ int  g_bsum[3 * SCAN_NB];
__device__ int  g_boff[3 * SCAN_NB];

static __device__ __forceinline__ const int* hist_of(int et) {
    return (et == 0) ? g_hist_f : (et == 1) ? g_hist_rb : g_hist_r;
}
static __device__ __forceinline__ int* ptr_of(int et) {
    return (et == 0) ? g_ptr_f : (et == 1) ? g_ptr_rb : g_ptr_r;
}
static __device__ __forceinline__ int* cur_of(int et) {
    return (et == 0) ? g_cur_f : (et == 1) ? g_cur_rb : g_cur_r;
}

// ---------------- zero histograms --------------------------------------------
__global__ void zero_hist_kernel() {
    int i = blockIdx.x * blockDim.x + threadIdx.x;
    if (i < NU) { g_hist_f[i] = 0; g_hist_rb[i] = 0; g_hist_r[i] = 0; }
}

// ---------------- fused histogram ---------------------------------------------
__global__ __launch_bounds__(256) void hist3_kernel(
    const int* __restrict__ d0, const int* __restrict__ d1,
    const int* __restrict__ d2, int E0, int E1, int E2)
{
    int et = blockIdx.y;
    const int* dst = (et == 0) ? d0 : (et == 1) ? d1 : d2;
    int* hist = (et == 0) ? g_hist_f : (et == 1) ? g_hist_rb : g_hist_r;
    int E = (et == 0) ? E0 : (et == 1) ? E1 : E2;
    int i = blockIdx.x * blockDim.x + threadIdx.x;
    if (i < E) atomicAdd(&hist[dst[i]], 1);
}

// ---------------- 3-phase full-chip exclusive scan ----------------------------
// phase 1: per-block sums (1024 elems/block)
__global__ __launch_bounds__(256) void scan_p1()
{
    int et = blockIdx.y;
    const int* hist = hist_of(et);
    int base = blockIdx.x * 1024;
    int i0 = base + threadIdx.x * 4;
    int s = 0;
#pragma unroll
    for (int j = 0; j < 4; j++)
        if (i0 + j < NROWS) s += hist[i0 + j];
    // block reduce
    int lane = threadIdx.x & 31, wid = threadIdx.x >> 5;
#pragma unroll
    for (int off = 16; off > 0; off >>= 1)
        s += __shfl_down_sync(0xffffffffu, s, off);
    __shared__ int ws[8];
    if (lane == 0) ws[wid] = s;
    __syncthreads();
    if (threadIdx.x == 0) {
        int tot = 0;
#pragma unroll
        for (int w = 0; w < 8; w++) tot += ws[w];
        g_bsum[et * SCAN_NB + blockIdx.x] = tot;
    }
}

// phase 2: tiny serial exclusive scan of block sums per etype; writes ptr[n]
__global__ void scan_p2()
{
    int et = threadIdx.x;   // 3 threads
    if (et >= 3) return;
    int run = 0;
    for (int b = 0; b < SCAN_NB; b++) {
        g_boff[et * SCAN_NB + b] = run;
        run += g_bsum[et * SCAN_NB + b];
    }
    ptr_of(et)[NROWS] = run;
}

// phase 3: block-local exclusive scan + block offset -> ptr/cur
__global__ __launch_bounds__(256) void scan_p3()
{
    int et = blockIdx.y;
    const int* hist = hist_of(et);
    int* ptr = ptr_of(et);
    int* cur = cur_of(et);
    int base = blockIdx.x * 1024;
    int i0 = base + threadIdx.x * 4;

    int h[4];
    int thsum = 0;
#pragma unroll
    for (int j = 0; j < 4; j++) {
        h[j] = (i0 + j < NROWS) ? hist[i0 + j] : 0;
        thsum += h[j];
    }
    int lane = threadIdx.x & 31, wid = threadIdx.x >> 5;
    int incl = thsum;
#pragma unroll
    for (int off = 1; off < 32; off <<= 1) {
        int t = __shfl_up_sync(0xffffffffu, incl, off);
        if (lane >= off) incl += t;
    }
    __shared__ int ws[8];
    if (lane == 31) ws[wid] = incl;
    __syncthreads();
    int wofs = 0;
#pragma unroll
    for (int w = 0; w < 8; w++)
        if (w < wid) wofs += ws[w];
    int excl = incl - thsum + wofs + g_boff[et * SCAN_NB + blockIdx.x];
#pragma unroll
    for (int j = 0; j < 4; j++) {
        if (i0 + j < NROWS) {
            ptr[i0 + j] = excl;
            cur[i0 + j] = excl;
        }
        excl += h[j];
    }
}

// ---------------- fused permute -----------------------------------------------
__global__ __launch_bounds__(256) void permute3_kernel(
    const int* __restrict__ s0, const int* __restrict__ d0,
    const int* __restrict__ s1, const int* __restrict__ d1,
    const int* __restrict__ s2, const int* __restrict__ d2,
    int E0, int E1, int E2)
{
    int et = blockIdx.y;
    const int* src = (et == 0) ? s0 : (et == 1) ? s1 : s2;
    const int* dst = (et == 0) ? d0 : (et == 1) ? d1 : d2;
    int* cur = cur_of(et);
    int* srclist = (et == 0) ? g_srcl_f : (et == 1) ? g_srcl_rb : g_srcl_r;
    int E = (et == 0) ? E0 : (et == 1) ? E1 : E2;
    int i = blockIdx.x * blockDim.x + threadIdx.x;
    if (i < E) {
        int d = dst[i];
        int p = atomicAdd(&cur[d], 1);
        srclist[p] = src[i];
    }
}

// ---------------- hi/lo bf16 split helpers ------------------------------------
static __device__ __forceinline__ void split_pack(float a, float b, u32& hi, u32& lo) {
    bf16 ha = __float2bfloat16_rn(a);
    bf16 hb = __float2bfloat16_rn(b);
    bf16 la = __float2bfloat16_rn(a - __bfloat162float(ha));
    bf16 lb = __float2bfloat16_rn(b - __bfloat162float(hb));
    hi = (u32)__bfloat16_as_ushort(ha) | ((u32)__bfloat16_as_ushort(hb) << 16);
    lo = (u32)__bfloat16_as_ushort(la) | ((u32)__bfloat16_as_ushort(lb) << 16);
}

// ---------------- W split prep -------------------------------------------------
__global__ void wprep_kernel(const float* __restrict__ Wf,
                             const float* __restrict__ Wrb,
                             const float* __restrict__ Wr)
{
    int et = blockIdx.x;
    const float* W = (et == 0) ? Wf : (et == 1) ? Wrb : Wr;
    bf16* wh = g_wh + et * D * D;
    bf16* wl = g_wl + et * D * D;
    for (int i = threadIdx.x; i < D * D; i += blockDim.x) {
        float x = W[i];
        bf16 h = __float2bfloat16_rn(x);
        wh[i] = h;
        wl[i] = __float2bfloat16_rn(x - __bfloat162float(h));
    }
}

// ---------------- fused gather (R5 form; writes bf16 hi/lo means) -------------
__global__ __launch_bounds__(256) void gather3_kernel(
    const float4* __restrict__ feat_u, const float4* __restrict__ feat_i)
{
    int et = blockIdx.y;
    const float4* feat = (et == 1) ? feat_i : feat_u;
    const int* ptr = (et == 0) ? g_ptr_f : (et == 1) ? g_ptr_rb : g_ptr_r;
    const int* srclist = (et == 0) ? g_srcl_f : (et == 1) ? g_srcl_rb : g_srcl_r;
    bf16* ah = (et == 0) ? g_ah_f : (et == 1) ? g_ah_rb : g_ah_r;
    bf16* al = (et == 0) ? g_al_f : (et == 1) ? g_al_rb : g_al_r;

    int node = (blockIdx.x * 256 + threadIdx.x) >> 5;
    int lane = threadIdx.x & 31;
    if (node >= NROWS) return;
    int beg = __ldg(&ptr[node]);
    int end = __ldg(&ptr[node + 1]);
    int deg = end - beg;

    float4 s = make_float4(0.f, 0.f, 0.f, 0.f);
    int e = beg;
    for (; e + 8 <= end; e += 8) {
        int si[8];
#pragma unroll
        for (int j = 0; j < 8; j++) si[j] = __ldg(&srclist[e + j]);
        float4 v[8];
#pragma unroll
        for (int j = 0; j < 8; j++) v[j] = feat[(size_t)si[j] * 32 + lane];
#pragma unroll
        for (int j = 0; j < 8; j++) {
            s.x += v[j].x; s.y += v[j].y; s.z += v[j].z; s.w += v[j].w;
        }
    }
    for (; e + 4 <= end; e += 4) {
        int si[4];
#pragma unroll
        for (int j = 0; j < 4; j++) si[j] = __ldg(&srclist[e + j]);
        float4 v[4];
#pragma unroll
        for (int j = 0; j < 4; j++) v[j] = feat[(size_t)si[j] * 32 + lane];
#pragma unroll
        for (int j = 0; j < 4; j++) {
            s.x += v[j].x; s.y += v[j].y; s.z += v[j].z; s.w += v[j].w;
        }
    }
    for (; e < end; e++) {
        float4 v = feat[(size_t)__ldg(&srclist[e]) * 32 + lane];
        s.x += v.x; s.y += v.y; s.z += v.z; s.w += v.w;
    }
    float inv = __fdividef(1.0f, (float)(deg > 0 ? deg : 1));
    s.x *= inv; s.y *= inv; s.z *= inv; s.w *= inv;

    u32 h0, l0, h1, l1;
    split_pack(s.x, s.y, h0, l0);
    split_pack(s.z, s.w, h1, l1);
    uint2 hv = make_uint2(h0, h1);
    uint2 lv = make_uint2(l0, l1);
    *reinterpret_cast<uint2*>(ah + (size_t)node * D + lane * 4) = hv;
    *reinterpret_cast<uint2*>(al + (size_t)node * D + lane * 4) = lv;
}

// ---------------- bf16 mma.sync GEMM ------------------------------------------
#define ASTR 72

static __device__ __forceinline__ void mma_bf16(float* c, const u32* a, u32 b0, u32 b1) {
    asm volatile(
        "mma.sync.aligned.m16n8k16.row.col.f32.bf16.bf16.f32 "
        "{%0,%1,%2,%3}, {%4,%5,%6,%7}, {%8,%9}, {%0,%1,%2,%3};"
        : "+f"(c[0]), "+f"(c[1]), "+f"(c[2]), "+f"(c[3])
        : "r"(a[0]), "r"(a[1]), "r"(a[2]), "r"(a[3]), "r"(b0), "r"(b1));
}

__global__ __launch_bounds__(256, 2) void gemm_mma(
    float* __restrict__ out_user, float* __restrict__ out_item,
    const float* __restrict__ b_f, const float* __restrict__ b_rb,
    const float* __restrict__ b_r)
{
    __shared__ __align__(16) bf16 As[128 * ASTR];
    __shared__ __align__(16) bf16 Bs[128 * ASTR];

    const int tid = threadIdx.x;
    const int wid = tid >> 5, lane = tid & 31;
    const int g = lane >> 2, t = lane & 3;
    const int row0 = blockIdx.x * 128;
    const bool user = (blockIdx.y == 0);

    const int wm0 = (wid >> 1) * 32;
    const int wn0 = (wid & 1) * 64;

    const bf16* APTR[6]; const bf16* WPTR[6];
    int npairs;
    if (user) {
        APTR[0] = g_ah_f;  WPTR[0] = g_wh;
        APTR[1] = g_al_f;  WPTR[1] = g_wh;
        APTR[2] = g_ah_f;  WPTR[2] = g_wl;
        APTR[3] = g_ah_rb; WPTR[3] = g_wh + D * D;
        APTR[4] = g_al_rb; WPTR[4] = g_wh + D * D;
        APTR[5] = g_ah_rb; WPTR[5] = g_wl + D * D;
        npairs = 6;
    } else {
        APTR[0] = g_ah_r;  WPTR[0] = g_wh + 2 * D * D;
        APTR[1] = g_al_r;  WPTR[1] = g_wh + 2 * D * D;
        APTR[2] = g_ah_r;  WPTR[2] = g_wl + 2 * D * D;
        npairs = 3;
    }

    float C[2][8][4];
#pragma unroll
    for (int mt = 0; mt < 2; mt++)
#pragma unroll
        for (int nt = 0; nt < 8; nt++)
#pragma unroll
            for (int q = 0; q < 4; q++) C[mt][nt][q] = 0.f;

    const int lrow = tid >> 1;
    const int lcol = (tid & 1) * 32;
    const bool arow_ok = (row0 + lrow < NROWS);

    for (int p = 0; p < npairs; p++) {
        const bf16* Asrc = APTR[p];
        const bf16* Wsrc = WPTR[p];
#pragma unroll
        for (int st = 0; st < 2; st++) {
            const int kc = st * 64;
            uint4 av[4], wv[4];
            const bf16* as = Asrc + (size_t)(row0 + lrow) * D + kc + lcol;
            const bf16* ws = Wsrc + (size_t)lrow * D + kc + lcol;
#pragma unroll
            for (int q = 0; q < 4; q++) {
                av[q] = arow_ok ? *reinterpret_cast<const uint4*>(as + q * 8)
                                : make_uint4(0u, 0u, 0u, 0u);
                wv[q] = *reinterpret_cast<const uint4*>(ws + q * 8);
            }
            __syncthreads();
#pragma unroll
            for (int q = 0; q < 4; q++) {
                *reinterpret_cast<uint4*>(&As[lrow * ASTR + lcol + q * 8]) = av[q];
                *reinterpret_cast<uint4*>(&Bs[lrow * ASTR + lcol + q * 8]) = wv[q];
            }
            __syncthreads();

#pragma unroll
            for (int ks = 0; ks < 4; ks++) {
                u32 a[2][4];
#pragma unroll
                for (int mt = 0; mt < 2; mt++) {
                    const bf16* ab = &As[(wm0 + mt * 16 + g) * ASTR + ks * 16 + t * 2];
                    a[mt][0] = *reinterpret_cast<const u32*>(ab);
                    a[mt][1] = *reinterpret_cast<const u32*>(ab + 8 * ASTR);
                    a[mt][2] = *reinterpret_cast<const u32*>(ab + 8);
                    a[mt][3] = *reinterpret_cast<const u32*>(ab + 8 * ASTR + 8);
                }
#pragma unroll
                for (int nt = 0; nt < 8; nt++) {
                    const bf16* bb = &Bs[(wn0 + nt * 8 + g) * ASTR + ks * 16 + t * 2];
                    u32 b0 = *reinterpret_cast<const u32*>(bb);
                    u32 b1 = *reinterpret_cast<const u32*>(bb + 8);
                    mma_bf16(C[0][nt], a[0], b0, b1);
                    mma_bf16(C[1][nt], a[1], b0, b1);
                }
            }
        }
    }

    const float* bias0 = user ? b_f : b_r;
    const int* cnt0 = user ? g_hist_f : g_hist_r;
    float* out = user ? out_user : out_item;
#pragma unroll
    for (int mt = 0; mt < 2; mt++) {
        int r0 = row0 + wm0 + mt * 16 + g;
        int r1 = r0 + 8;
        bool ok0 = (r0 < NROWS), ok1 = (r1 < NROWS);
        float m00 = (ok0 && cnt0[ok0 ? r0 : 0] > 0) ? 1.f : 0.f;
        float m01 = (ok1 && cnt0[ok1 ? r1 : 0] > 0) ? 1.f : 0.f;
        float m10 = (user && ok0 && g_hist_rb[ok0 ? r0 : 0] > 0) ? 1.f : 0.f;
        float m11 = (user && ok1 && g_hist_rb[ok1 ? r1 : 0] > 0) ? 1.f : 0.f;
#pragma unroll
        for (int nt = 0; nt < 8; nt++) {
            int col = wn0 + nt * 8 + t * 2;
            float bb0 = bias0[col], bb1 = bias0[col + 1];
            float br0 = user ? b_rb[col] : 0.f;
            float br1 = user ? b_rb[col + 1] : 0.f;
            if (ok0) {
                float2 v;
                v.x = C[mt][nt][0] + bb0 * m00 + br0 * m10;
                v.y = C[mt][nt][1] + bb1 * m00 + br1 * m10;
                *reinterpret_cast<float2*>(out + (size_t)r0 * D + col) = v;
            }
            if (ok1) {
                float2 v;
                v.x = C[mt][nt][2] + bb0 * m01 + br0 * m11;
                v.y = C[mt][nt][3] + bb1 * m01 + br1 * m11;
                *reinterpret_cast<float2*>(out + (size_t)r1 * D + col) = v;
            }
        }
    }
}

// ---------------- launch ------------------------------------------------------
extern "C" void kernel_launch(void* const* d_in, const int* in_sizes, int n_in,
                              void* d_out, int out_size)
{
    const float* feat_user = (const float*)d_in[0];
    const float* feat_item = (const float*)d_in[1];
    const float* W_f  = (const float*)d_in[2];
    const float* b_f  = (const float*)d_in[3];
    const float* W_r  = (const float*)d_in[4];
    const float* b_r  = (const float*)d_in[5];
    const float* W_rb = (const float*)d_in[6];
    const float* b_rb = (const float*)d_in[7];
    const int* src_f  = (const int*)d_in[8];
    const int* dst_f  = (const int*)d_in[9];
    const int* src_r  = (const int*)d_in[10];
    const int* dst_r  = (const int*)d_in[11];
    const int* src_rb = (const int*)d_in[12];
    const int* dst_rb = (const int*)d_in[13];
    const int E_f  = in_sizes[8];
    const int E_rb = in_sizes[12];
    const int E_r  = in_sizes[10];

    float* out_user = (float*)d_out;
    float* out_item = (float*)d_out + (size_t)NU * D;

    int Emax = E_f > E_rb ? E_f : E_rb;
    if (E_r > Emax) Emax = E_r;

    zero_hist_kernel<<<(NU + 255) / 256, 256>>>();

    {
        dim3 g((Emax + 255) / 256, 3);
        hist3_kernel<<<g, 256>>>(dst_f, dst_rb, dst_r, E_f, E_rb, E_r);
    }

    wprep_kernel<<<3, 256>>>(W_f, W_rb, W_r);

    {
        dim3 g(SCAN_NB, 3);
        scan_p1<<<g, 256>>>();
        scan_p2<<<1, 3>>>();
        scan_p3<<<g, 256>>>();
    }

    {
        dim3 g((Emax + 255) / 256, 3);
        permute3_kernel<<<g, 256>>>(src_f, dst_f, src_rb, dst_rb, src_r, dst_r,
                                    E_f, E_rb, E_r);
    }

    {
        dim3 g((NROWS * 32 + 255) / 256, 3);
        gather3_kernel<<<g, 256>>>((const float4*)feat_user,
                                   (const float4*)feat_item);
    }

    {
        dim3 g((NROWS + 127) / 128, 2);
        gemm_mma<<<g, 256>>>(out_user, out_item, b_f, b_rb, b_r);
    }
}

// round 13
// speedup vs baseline: 2.8046x; 1.0393x over previous
#include <cuda_runtime.h>
#include <cuda_bf16.h>
#include <cstdint>

#define NU 100000
#define NI 100000
#define D  128
#define EMAX 810000
#define NROWS 100000
#define SCAN_NB ((NROWS + 1023) / 1024)

typedef __nv_bfloat16 bf16;
typedef unsigned int u32;

// ---------------- scratch ----------------------------------------------------
__device__ bf16 g_ah_f [(size_t)NU * D];
__device__ bf16 g_al_f [(size_t)NU * D];
__device__ bf16 g_ah_rb[(size_t)NU * D];
__device__ bf16 g_al_rb[(size_t)NU * D];
__device__ bf16 g_ah_r [(size_t)NI * D];
__device__ bf16 g_al_r [(size_t)NI * D];
__device__ bf16 g_wh[3 * D * D];
__device__ bf16 g_wl[3 * D * D];
__device__ int  g_hist_f [NU];
__device__ int  g_hist_rb[NU];
__device__ int  g_hist_r [NI];
__device__ int  g_ptr_f [NU + 1];
__device__ int  g_ptr_rb[NU + 1];
__device__ int  g_ptr_r [NI + 1];
__device__ int  g_cur_f [NU];
__device__ int  g_cur_rb[NU];
__device__ int  g_cur_r [NI];
__device__ int  g_srcl_f [EMAX];
__device__ int  g_srcl_rb[EMAX];
__device__ int  g_srcl_r [EMAX];
__device__ int  g_bsum[3 * SCAN_NB];
__device__ int  g_boff[3 * SCAN_NB];

static __device__ __forceinline__ const int* hist_of(int et) {
    return (et == 0) ? g_hist_f : (et == 1) ? g_hist_rb : g_hist_r;
}
static __device__ __forceinline__ int* ptr_of(int et) {
    return (et == 0) ? g_ptr_f : (et == 1) ? g_ptr_rb : g_ptr_r;
}
static __device__ __forceinline__ int* cur_of(int et) {
    return (et == 0) ? g_cur_f : (et == 1) ? g_cur_rb : g_cur_r;
}

// ---------------- zero histograms --------------------------------------------
__global__ void zero_hist_kernel() {
    int i = blockIdx.x * blockDim.x + threadIdx.x;
    if (i < NU) { g_hist_f[i] = 0; g_hist_rb[i] = 0; g_hist_r[i] = 0; }
}

// ---------------- fused histogram ---------------------------------------------
__global__ __launch_bounds__(256) void hist3_kernel(
    const int* __restrict__ d0, const int* __restrict__ d1,
    const int* __restrict__ d2, int E0, int E1, int E2)
{
    int et = blockIdx.y;
    const int* dst = (et == 0) ? d0 : (et == 1) ? d1 : d2;
    int* hist = (et == 0) ? g_hist_f : (et == 1) ? g_hist_rb : g_hist_r;
    int E = (et == 0) ? E0 : (et == 1) ? E1 : E2;
    int i = blockIdx.x * blockDim.x + threadIdx.x;
    if (i < E) atomicAdd(&hist[dst[i]], 1);
}

// ---------------- 3-phase full-chip exclusive scan ----------------------------
__global__ __launch_bounds__(256) void scan_p1()
{
    int et = blockIdx.y;
    const int* hist = hist_of(et);
    int i0 = blockIdx.x * 1024 + threadIdx.x * 4;
    int s = 0;
#pragma unroll
    for (int j = 0; j < 4; j++)
        if (i0 + j < NROWS) s += hist[i0 + j];
    int lane = threadIdx.x & 31, wid = threadIdx.x >> 5;
#pragma unroll
    for (int off = 16; off > 0; off >>= 1)
        s += __shfl_down_sync(0xffffffffu, s, off);
    __shared__ int ws[8];
    if (lane == 0) ws[wid] = s;
    __syncthreads();
    if (threadIdx.x == 0) {
        int tot = 0;
#pragma unroll
        for (int w = 0; w < 8; w++) tot += ws[w];
        g_bsum[et * SCAN_NB + blockIdx.x] = tot;
    }
}

__global__ void scan_p2()
{
    int et = threadIdx.x;
    if (et >= 3) return;
    int run = 0;
    for (int b = 0; b < SCAN_NB; b++) {
        g_boff[et * SCAN_NB + b] = run;
        run += g_bsum[et * SCAN_NB + b];
    }
    ptr_of(et)[NROWS] = run;
}

__global__ __launch_bounds__(256) void scan_p3()
{
    int et = blockIdx.y;
    const int* hist = hist_of(et);
    int* ptr = ptr_of(et);
    int* cur = cur_of(et);
    int i0 = blockIdx.x * 1024 + threadIdx.x * 4;

    int h[4];
    int thsum = 0;
#pragma unroll
    for (int j = 0; j < 4; j++) {
        h[j] = (i0 + j < NROWS) ? hist[i0 + j] : 0;
        thsum += h[j];
    }
    int lane = threadIdx.x & 31, wid = threadIdx.x >> 5;
    int incl = thsum;
#pragma unroll
    for (int off = 1; off < 32; off <<= 1) {
        int t = __shfl_up_sync(0xffffffffu, incl, off);
        if (lane >= off) incl += t;
    }
    __shared__ int ws[8];
    if (lane == 31) ws[wid] = incl;
    __syncthreads();
    int wofs = 0;
#pragma unroll
    for (int w = 0; w < 8; w++)
        if (w < wid) wofs += ws[w];
    int excl = incl - thsum + wofs + g_boff[et * SCAN_NB + blockIdx.x];
#pragma unroll
    for (int j = 0; j < 4; j++) {
        if (i0 + j < NROWS) {
            ptr[i0 + j] = excl;
            cur[i0 + j] = excl;
        }
        excl += h[j];
    }
}

// ---------------- fused permute -----------------------------------------------
__global__ __launch_bounds__(256) void permute3_kernel(
    const int* __restrict__ s0, const int* __restrict__ d0,
    const int* __restrict__ s1, const int* __restrict__ d1,
    const int* __restrict__ s2, const int* __restrict__ d2,
    int E0, int E1, int E2)
{
    int et = blockIdx.y;
    const int* src = (et == 0) ? s0 : (et == 1) ? s1 : s2;
    const int* dst = (et == 0) ? d0 : (et == 1) ? d1 : d2;
    int* cur = cur_of(et);
    int* srclist = (et == 0) ? g_srcl_f : (et == 1) ? g_srcl_rb : g_srcl_r;
    int E = (et == 0) ? E0 : (et == 1) ? E1 : E2;
    int i = blockIdx.x * blockDim.x + threadIdx.x;
    if (i < E) {
        int d = dst[i];
        int p = atomicAdd(&cur[d], 1);
        srclist[p] = src[i];
    }
}

// ---------------- hi/lo bf16 split helpers ------------------------------------
static __device__ __forceinline__ void split_pack(float a, float b, u32& hi, u32& lo) {
    bf16 ha = __float2bfloat16_rn(a);
    bf16 hb = __float2bfloat16_rn(b);
    bf16 la = __float2bfloat16_rn(a - __bfloat162float(ha));
    bf16 lb = __float2bfloat16_rn(b - __bfloat162float(hb));
    hi = (u32)__bfloat16_as_ushort(ha) | ((u32)__bfloat16_as_ushort(hb) << 16);
    lo = (u32)__bfloat16_as_ushort(la) | ((u32)__bfloat16_as_ushort(lb) << 16);
}

// ---------------- W split prep -------------------------------------------------
__global__ void wprep_kernel(const float* __restrict__ Wf,
                             const float* __restrict__ Wrb,
                             const float* __restrict__ Wr)
{
    int et = blockIdx.x;
    const float* W = (et == 0) ? Wf : (et == 1) ? Wrb : Wr;
    bf16* wh = g_wh + et * D * D;
    bf16* wl = g_wl + et * D * D;
    for (int i = threadIdx.x; i < D * D; i += blockDim.x) {
        float x = W[i];
        bf16 h = __float2bfloat16_rn(x);
        wh[i] = h;
        wl[i] = __float2bfloat16_rn(x - __bfloat162float(h));
    }
}

// ---------------- fused gather (R5 form; writes bf16 hi/lo means) -------------
__global__ __launch_bounds__(256) void gather3_kernel(
    const float4* __restrict__ feat_u, const float4* __restrict__ feat_i)
{
    int et = blockIdx.y;
    const float4* feat = (et == 1) ? feat_i : feat_u;
    const int* ptr = (et == 0) ? g_ptr_f : (et == 1) ? g_ptr_rb : g_ptr_r;
    const int* srclist = (et == 0) ? g_srcl_f : (et == 1) ? g_srcl_rb : g_srcl_r;
    bf16* ah = (et == 0) ? g_ah_f : (et == 1) ? g_ah_rb : g_ah_r;
    bf16* al = (et == 0) ? g_al_f : (et == 1) ? g_al_rb : g_al_r;

    int node = (blockIdx.x * 256 + threadIdx.x) >> 5;
    int lane = threadIdx.x & 31;
    if (node >= NROWS) return;
    int beg = __ldg(&ptr[node]);
    int end = __ldg(&ptr[node + 1]);
    int deg = end - beg;

    float4 s = make_float4(0.f, 0.f, 0.f, 0.f);
    int e = beg;
    for (; e + 8 <= end; e += 8) {
        int si[8];
#pragma unroll
        for (int j = 0; j < 8; j++) si[j] = __ldg(&srclist[e + j]);
        float4 v[8];
#pragma unroll
        for (int j = 0; j < 8; j++) v[j] = feat[(size_t)si[j] * 32 + lane];
#pragma unroll
        for (int j = 0; j < 8; j++) {
            s.x += v[j].x; s.y += v[j].y; s.z += v[j].z; s.w += v[j].w;
        }
    }
    for (; e + 4 <= end; e += 4) {
        int si[4];
#pragma unroll
        for (int j = 0; j < 4; j++) si[j] = __ldg(&srclist[e + j]);
        float4 v[4];
#pragma unroll
        for (int j = 0; j < 4; j++) v[j] = feat[(size_t)si[j] * 32 + lane];
#pragma unroll
        for (int j = 0; j < 4; j++) {
            s.x += v[j].x; s.y += v[j].y; s.z += v[j].z; s.w += v[j].w;
        }
    }
    for (; e < end; e++) {
        float4 v = feat[(size_t)__ldg(&srclist[e]) * 32 + lane];
        s.x += v.x; s.y += v.y; s.z += v.z; s.w += v.w;
    }
    float inv = __fdividef(1.0f, (float)(deg > 0 ? deg : 1));
    s.x *= inv; s.y *= inv; s.z *= inv; s.w *= inv;

    u32 h0, l0, h1, l1;
    split_pack(s.x, s.y, h0, l0);
    split_pack(s.z, s.w, h1, l1);
    *reinterpret_cast<uint2*>(ah + (size_t)node * D + lane * 4) = make_uint2(h0, h1);
    *reinterpret_cast<uint2*>(al + (size_t)node * D + lane * 4) = make_uint2(l0, l1);
}

// ---------------- bf16 mma.sync GEMM with ldmatrix + A-reuse -----------------
#define ASTR 72   // bf16 row stride (144 B): 16B-aligned rows, conflict-free LDSM

static __device__ __forceinline__ void mma_bf16(float* c, const u32* a, u32 b0, u32 b1) {
    asm volatile(
        "mma.sync.aligned.m16n8k16.row.col.f32.bf16.bf16.f32 "
        "{%0,%1,%2,%3}, {%4,%5,%6,%7}, {%8,%9}, {%0,%1,%2,%3};"
        : "+f"(c[0]), "+f"(c[1]), "+f"(c[2]), "+f"(c[3])
        : "r"(a[0]), "r"(a[1]), "r"(a[2]), "r"(a[3]), "r"(b0), "r"(b1));
}
static __device__ __forceinline__ void ldsm_x4(u32& d0, u32& d1, u32& d2, u32& d3, u32 addr) {
    asm volatile("ldmatrix.sync.aligned.m8n8.x4.shared.b16 {%0,%1,%2,%3}, [%4];"
                 : "=r"(d0), "=r"(d1), "=r"(d2), "=r"(d3) : "r"(addr));
}

__global__ __launch_bounds__(256, 2) void gemm_mma(
    float* __restrict__ out_user, float* __restrict__ out_item,
    const float* __restrict__ b_f, const float* __restrict__ b_rb,
    const float* __restrict__ b_r)
{
    __shared__ __align__(16) bf16 As[128 * ASTR];
    __shared__ __align__(16) bf16 Bs[128 * ASTR];

    const int tid = threadIdx.x;
    const int wid = tid >> 5, lane = tid & 31;
    const int g = lane >> 2, t = lane & 3;
    const int q = lane >> 3, rr = lane & 7;   // ldmatrix lane roles
    const int row0 = blockIdx.x * 128;
    const bool user = (blockIdx.y == 0);
    const int nsegs = user ? 2 : 1;

    const int wm0 = (wid >> 1) * 32;
    const int wn0 = (wid & 1) * 64;

    float C[2][8][4];
#pragma unroll
    for (int mt = 0; mt < 2; mt++)
#pragma unroll
        for (int nt = 0; nt < 8; nt++)
#pragma unroll
            for (int qq = 0; qq < 4; qq++) C[mt][nt][qq] = 0.f;

    // staging mapping: row = tid>>1, 32-bf16 half per thread
    const int lrow = tid >> 1;
    const int lcol = (tid & 1) * 32;
    const bool arow_ok = (row0 + lrow < NROWS);

    // ldmatrix base addresses (u32 shared-space), advance by ks*32 bytes per kstep
    const u32 as_b = (u32)__cvta_generic_to_shared(As);
    const u32 bs_b = (u32)__cvta_generic_to_shared(Bs);
    u32 a_ad[2], b_ad[4];
#pragma unroll
    for (int mt = 0; mt < 2; mt++)
        a_ad[mt] = as_b + ((wm0 + mt * 16 + (q & 1) * 8 + rr) * ASTR + (q >> 1) * 8) * 2;
#pragma unroll
    for (int np = 0; np < 4; np++)
        b_ad[np] = bs_b + ((wn0 + (np * 2 + (q >> 1)) * 8 + rr) * ASTR + (q & 1) * 8) * 2;

#define STAGE_A(Asrc, kc)                                                        \
    {                                                                            \
        const bf16* as_ = (Asrc) + (size_t)(row0 + lrow) * D + (kc) + lcol;      \
        uint4 av[4];                                                             \
        _Pragma("unroll")                                                        \
        for (int qq = 0; qq < 4; qq++)                                           \
            av[qq] = arow_ok ? *reinterpret_cast<const uint4*>(as_ + qq * 8)     \
                             : make_uint4(0u, 0u, 0u, 0u);                       \
        _Pragma("unroll")                                                        \
        for (int qq = 0; qq < 4; qq++)                                           \
            *reinterpret_cast<uint4*>(&As[lrow * ASTR + lcol + qq * 8]) = av[qq];\
    }
#define STAGE_B(Wsrc, kc)                                                        \
    {                                                                            \
        const bf16* ws_ = (Wsrc) + (size_t)lrow * D + (kc) + lcol;               \
        uint4 wv[4];                                                             \
        _Pragma("unroll")                                                        \
        for (int qq = 0; qq < 4; qq++)                                           \
            wv[qq] = *reinterpret_cast<const uint4*>(ws_ + qq * 8);              \
        _Pragma("unroll")                                                        \
        for (int qq = 0; qq < 4; qq++)                                           \
            *reinterpret_cast<uint4*>(&Bs[lrow * ASTR + lcol + qq * 8]) = wv[qq];\
    }
#define MMA_PASS()                                                               \
    {                                                                            \
        _Pragma("unroll")                                                        \
        for (int ks = 0; ks < 4; ks++) {                                         \
            u32 af[2][4];                                                        \
            ldsm_x4(af[0][0], af[0][1], af[0][2], af[0][3], a_ad[0] + ks * 32);  \
            ldsm_x4(af[1][0], af[1][1], af[1][2], af[1][3], a_ad[1] + ks * 32);  \
            u32 bf_[4][4];                                                       \
            _Pragma("unroll")                                                    \
            for (int np = 0; np < 4; np++)                                       \
                ldsm_x4(bf_[np][0], bf_[np][1], bf_[np][2], bf_[np][3],          \
                        b_ad[np] + ks * 32);                                     \
            _Pragma("unroll")                                                    \
            for (int nt = 0; nt < 8; nt++) {                                     \
                u32 b0 = bf_[nt >> 1][(nt & 1) * 2];                             \
                u32 b1 = bf_[nt >> 1][(nt & 1) * 2 + 1];                         \
                mma_bf16(C[0][nt], af[0], b0, b1);                               \
                mma_bf16(C[1][nt], af[1], b0, b1);                               \
            }                                                                    \
        }                                                                        \
    }

    for (int seg = 0; seg < nsegs; seg++) {
        const int we = user ? seg : 2;
        const bf16* Ah = user ? (seg ? g_ah_rb : g_ah_f) : g_ah_r;
        const bf16* Al = user ? (seg ? g_al_rb : g_al_f) : g_al_r;
        const bf16* Wh = g_wh + we * D * D;
        const bf16* Wl = g_wl + we * D * D;
#pragma unroll
        for (int st = 0; st < 2; st++) {
            const int kc = st * 64;
            // pass 1: Ah · Wh
            __syncthreads();
            STAGE_A(Ah, kc);
            STAGE_B(Wh, kc);
            __syncthreads();
            MMA_PASS();
            // pass 2: Ah · Wl (A stays resident)
            __syncthreads();
            STAGE_B(Wl, kc);
            __syncthreads();
            MMA_PASS();
            // pass 3: Al · Wh
            __syncthreads();
            STAGE_A(Al, kc);
            STAGE_B(Wh, kc);
            __syncthreads();
            MMA_PASS();
        }
    }

    // epilogue: masked biases, direct stores
    const float* bias0 = user ? b_f : b_r;
    const int* cnt0 = user ? g_hist_f : g_hist_r;
    float* out = user ? out_user : out_item;
#pragma unroll
    for (int mt = 0; mt < 2; mt++) {
        int r0 = row0 + wm0 + mt * 16 + g;
        int r1 = r0 + 8;
        bool ok0 = (r0 < NROWS), ok1 = (r1 < NROWS);
        float m00 = (ok0 && cnt0[ok0 ? r0 : 0] > 0) ? 1.f : 0.f;
        float m01 = (ok1 && cnt0[ok1 ? r1 : 0] > 0) ? 1.f : 0.f;
        float m10 = (user && ok0 && g_hist_rb[ok0 ? r0 : 0] > 0) ? 1.f : 0.f;
        float m11 = (user && ok1 && g_hist_rb[ok1 ? r1 : 0] > 0) ? 1.f : 0.f;
#pragma unroll
        for (int nt = 0; nt < 8; nt++) {
            int col = wn0 + nt * 8 + t * 2;
            float bb0 = bias0[col], bb1 = bias0[col + 1];
            float br0 = user ? b_rb[col] : 0.f;
            float br1 = user ? b_rb[col + 1] : 0.f;
            if (ok0) {
                float2 v;
                v.x = C[mt][nt][0] + bb0 * m00 + br0 * m10;
                v.y = C[mt][nt][1] + bb1 * m00 + br1 * m10;
                *reinterpret_cast<float2*>(out + (size_t)r0 * D + col) = v;
            }
            if (ok1) {
                float2 v;
                v.x = C[mt][nt][2] + bb0 * m01 + br0 * m11;
                v.y = C[mt][nt][3] + bb1 * m01 + br1 * m11;
                *reinterpret_cast<float2*>(out + (size_t)r1 * D + col) = v;
            }
        }
    }
}

// ---------------- launch ------------------------------------------------------
extern "C" void kernel_launch(void* const* d_in, const int* in_sizes, int n_in,
                              void* d_out, int out_size)
{
    const float* feat_user = (const float*)d_in[0];
    const float* feat_item = (const float*)d_in[1];
    const float* W_f  = (const float*)d_in[2];
    const float* b_f  = (const float*)d_in[3];
    const float* W_r  = (const float*)d_in[4];
    const float* b_r  = (const float*)d_in[5];
    const float* W_rb = (const float*)d_in[6];
    const float* b_rb = (const float*)d_in[7];
    const int* src_f  = (const int*)d_in[8];
    const int* dst_f  = (const int*)d_in[9];
    const int* src_r  = (const int*)d_in[10];
    const int* dst_r  = (const int*)d_in[11];
    const int* src_rb = (const int*)d_in[12];
    const int* dst_rb = (const int*)d_in[13];
    const int E_f  = in_sizes[8];
    const int E_rb = in_sizes[12];
    const int E_r  = in_sizes[10];

    float* out_user = (float*)d_out;
    float* out_item = (float*)d_out + (size_t)NU * D;

    int Emax = E_f > E_rb ? E_f : E_rb;
    if (E_r > Emax) Emax = E_r;

    zero_hist_kernel<<<(NU + 255) / 256, 256>>>();

    {
        dim3 g((Emax + 255) / 256, 3);
        hist3_kernel<<<g, 256>>>(dst_f, dst_rb, dst_r, E_f, E_rb, E_r);
    }

    wprep_kernel<<<3, 256>>>(W_f, W_rb, W_r);

    {
        dim3 g(SCAN_NB, 3);
        scan_p1<<<g, 256>>>();
        scan_p2<<<1, 3>>>();
        scan_p3<<<g, 256>>>();
    }

    {
        dim3 g((Emax + 255) / 256, 3);
        permute3_kernel<<<g, 256>>>(src_f, dst_f, src_rb, dst_rb, src_r, dst_r,
                                    E_f, E_rb, E_r);
    }

    {
        dim3 g((NROWS * 32 + 255) / 256, 3);
        gather3_kernel<<<g, 256>>>((const float4*)feat_user,
                                   (const float4*)feat_item);
    }

    {
        dim3 g((NROWS + 127) / 128, 2);
        gemm_mma<<<g, 256>>>(out_user, out_item, b_f, b_rb, b_r);
    }
}

// round 14
// speedup vs baseline: 3.7536x; 1.3383x over previous
#include <cuda_runtime.h>
#include <cuda_fp16.h>
#include <cstdint>

#define NU 100000
#define NI 100000
#define D  128
#define EMAX 810000
#define NROWS 100000
#define SCAN_NB ((NROWS + 1023) / 1024)

typedef __half h16;
typedef unsigned int u32;

// ---------------- scratch ----------------------------------------------------
__device__ h16 g_a_f [(size_t)NU * D];
__device__ h16 g_a_rb[(size_t)NU * D];
__device__ h16 g_a_r [(size_t)NI * D];
__device__ h16 g_w16[3 * D * D];
__device__ int g_hist_f [NU];
__device__ int g_hist_rb[NU];
__device__ int g_hist_r [NI];
__device__ int g_ptr_f [NU + 1];
__device__ int g_ptr_rb[NU + 1];
__device__ int g_ptr_r [NI + 1];
__device__ int g_cur_f [NU];
__device__ int g_cur_rb[NU];
__device__ int g_cur_r [NI];
__device__ int g_srcl_f [EMAX];
__device__ int g_srcl_rb[EMAX];
__device__ int g_srcl_r [EMAX];
__device__ int g_bsum[3 * SCAN_NB];
__device__ int g_boff[3 * SCAN_NB];

static __device__ __forceinline__ const int* hist_of(int et) {
    return (et == 0) ? g_hist_f : (et == 1) ? g_hist_rb : g_hist_r;
}
static __device__ __forceinline__ int* ptr_of(int et) {
    return (et == 0) ? g_ptr_f : (et == 1) ? g_ptr_rb : g_ptr_r;
}
static __device__ __forceinline__ int* cur_of(int et) {
    return (et == 0) ? g_cur_f : (et == 1) ? g_cur_rb : g_cur_r;
}

// ---------------- zero histograms --------------------------------------------
__global__ void zero_hist_kernel() {
    int i = blockIdx.x * blockDim.x + threadIdx.x;
    if (i < NU) { g_hist_f[i] = 0; g_hist_rb[i] = 0; g_hist_r[i] = 0; }
}

// ---------------- fused histogram ---------------------------------------------
__global__ __launch_bounds__(256) void hist3_kernel(
    const int* __restrict__ d0, const int* __restrict__ d1,
    const int* __restrict__ d2, int E0, int E1, int E2)
{
    int et = blockIdx.y;
    const int* dst = (et == 0) ? d0 : (et == 1) ? d1 : d2;
    int* hist = (et == 0) ? g_hist_f : (et == 1) ? g_hist_rb : g_hist_r;
    int E = (et == 0) ? E0 : (et == 1) ? E1 : E2;
    int i = blockIdx.x * blockDim.x + threadIdx.x;
    if (i < E) atomicAdd(&hist[dst[i]], 1);
}

// ---------------- 3-phase full-chip exclusive scan ----------------------------
__global__ __launch_bounds__(256) void scan_p1()
{
    int et = blockIdx.y;
    const int* hist = hist_of(et);
    int i0 = blockIdx.x * 1024 + threadIdx.x * 4;
    int s = 0;
#pragma unroll
    for (int j = 0; j < 4; j++)
        if (i0 + j < NROWS) s += hist[i0 + j];
    int lane = threadIdx.x & 31, wid = threadIdx.x >> 5;
#pragma unroll
    for (int off = 16; off > 0; off >>= 1)
        s += __shfl_down_sync(0xffffffffu, s, off);
    __shared__ int ws[8];
    if (lane == 0) ws[wid] = s;
    __syncthreads();
    if (threadIdx.x == 0) {
        int tot = 0;
#pragma unroll
        for (int w = 0; w < 8; w++) tot += ws[w];
        g_bsum[et * SCAN_NB + blockIdx.x] = tot;
    }
}

__global__ void scan_p2()
{
    int et = threadIdx.x;
    if (et >= 3) return;
    int run = 0;
    for (int b = 0; b < SCAN_NB; b++) {
        g_boff[et * SCAN_NB + b] = run;
        run += g_bsum[et * SCAN_NB + b];
    }
    ptr_of(et)[NROWS] = run;
}

__global__ __launch_bounds__(256) void scan_p3()
{
    int et = blockIdx.y;
    const int* hist = hist_of(et);
    int* ptr = ptr_of(et);
    int* cur = cur_of(et);
    int i0 = blockIdx.x * 1024 + threadIdx.x * 4;

    int h[4];
    int thsum = 0;
#pragma unroll
    for (int j = 0; j < 4; j++) {
        h[j] = (i0 + j < NROWS) ? hist[i0 + j] : 0;
        thsum += h[j];
    }
    int lane = threadIdx.x & 31, wid = threadIdx.x >> 5;
    int incl = thsum;
#pragma unroll
    for (int off = 1; off < 32; off <<= 1) {
        int t = __shfl_up_sync(0xffffffffu, incl, off);
        if (lane >= off) incl += t;
    }
    __shared__ int ws[8];
    if (lane == 31) ws[wid] = incl;
    __syncthreads();
    int wofs = 0;
#pragma unroll
    for (int w = 0; w < 8; w++)
        if (w < wid) wofs += ws[w];
    int excl = incl - thsum + wofs + g_boff[et * SCAN_NB + blockIdx.x];
#pragma unroll
    for (int j = 0; j < 4; j++) {
        if (i0 + j < NROWS) {
            ptr[i0 + j] = excl;
            cur[i0 + j] = excl;
        }
        excl += h[j];
    }
}

// ---------------- fused permute -----------------------------------------------
__global__ __launch_bounds__(256) void permute3_kernel(
    const int* __restrict__ s0, const int* __restrict__ d0,
    const int* __restrict__ s1, const int* __restrict__ d1,
    const int* __restrict__ s2, const int* __restrict__ d2,
    int E0, int E1, int E2)
{
    int et = blockIdx.y;
    const int* src = (et == 0) ? s0 : (et == 1) ? s1 : s2;
    const int* dst = (et == 0) ? d0 : (et == 1) ? d1 : d2;
    int* cur = cur_of(et);
    int* srclist = (et == 0) ? g_srcl_f : (et == 1) ? g_srcl_rb : g_srcl_r;
    int E = (et == 0) ? E0 : (et == 1) ? E1 : E2;
    int i = blockIdx.x * blockDim.x + threadIdx.x;
    if (i < E) {
        int d = dst[i];
        int p = atomicAdd(&cur[d], 1);
        srclist[p] = src[i];
    }
}

// ---------------- W fp16 prep --------------------------------------------------
__global__ void wprep_kernel(const float* __restrict__ Wf,
                             const float* __restrict__ Wrb,
                             const float* __restrict__ Wr)
{
    int et = blockIdx.x;
    const float* W = (et == 0) ? Wf : (et == 1) ? Wrb : Wr;
    h16* w = g_w16 + et * D * D;
    for (int i = threadIdx.x; i < D * D; i += blockDim.x)
        w[i] = __float2half_rn(W[i]);
}

// ---------------- fused gather (R5 form; writes fp16 means) -------------------
__global__ __launch_bounds__(256) void gather3_kernel(
    const float4* __restrict__ feat_u, const float4* __restrict__ feat_i)
{
    int et = blockIdx.y;
    const float4* feat = (et == 1) ? feat_i : feat_u;
    const int* ptr = (et == 0) ? g_ptr_f : (et == 1) ? g_ptr_rb : g_ptr_r;
    const int* srclist = (et == 0) ? g_srcl_f : (et == 1) ? g_srcl_rb : g_srcl_r;
    h16* a = (et == 0) ? g_a_f : (et == 1) ? g_a_rb : g_a_r;

    int node = (blockIdx.x * 256 + threadIdx.x) >> 5;
    int lane = threadIdx.x & 31;
    if (node >= NROWS) return;
    int beg = __ldg(&ptr[node]);
    int end = __ldg(&ptr[node + 1]);
    int deg = end - beg;

    float4 s = make_float4(0.f, 0.f, 0.f, 0.f);
    int e = beg;
    for (; e + 8 <= end; e += 8) {
        int si[8];
#pragma unroll
        for (int j = 0; j < 8; j++) si[j] = __ldg(&srclist[e + j]);
        float4 v[8];
#pragma unroll
        for (int j = 0; j < 8; j++) v[j] = feat[(size_t)si[j] * 32 + lane];
#pragma unroll
        for (int j = 0; j < 8; j++) {
            s.x += v[j].x; s.y += v[j].y; s.z += v[j].z; s.w += v[j].w;
        }
    }
    for (; e + 4 <= end; e += 4) {
        int si[4];
#pragma unroll
        for (int j = 0; j < 4; j++) si[j] = __ldg(&srclist[e + j]);
        float4 v[4];
#pragma unroll
        for (int j = 0; j < 4; j++) v[j] = feat[(size_t)si[j] * 32 + lane];
#pragma unroll
        for (int j = 0; j < 4; j++) {
            s.x += v[j].x; s.y += v[j].y; s.z += v[j].z; s.w += v[j].w;
        }
    }
    for (; e < end; e++) {
        float4 v = feat[(size_t)__ldg(&srclist[e]) * 32 + lane];
        s.x += v.x; s.y += v.y; s.z += v.z; s.w += v.w;
    }
    float inv = __fdividef(1.0f, (float)(deg > 0 ? deg : 1));

    u32 p0 = (u32)__half_as_ushort(__float2half_rn(s.x * inv))
           | ((u32)__half_as_ushort(__float2half_rn(s.y * inv)) << 16);
    u32 p1 = (u32)__half_as_ushort(__float2half_rn(s.z * inv))
           | ((u32)__half_as_ushort(__float2half_rn(s.w * inv)) << 16);
    *reinterpret_cast<uint2*>(a + (size_t)node * D + lane * 4) = make_uint2(p0, p1);
}

// ---------------- fp16 mma.sync GEMM (single product) -------------------------
#define ASTR 72   // h16 row stride (144 B): 16B-aligned rows, conflict-free LDSM

static __device__ __forceinline__ void mma_f16(float* c, const u32* a, u32 b0, u32 b1) {
    asm volatile(
        "mma.sync.aligned.m16n8k16.row.col.f32.f16.f16.f32 "
        "{%0,%1,%2,%3}, {%4,%5,%6,%7}, {%8,%9}, {%0,%1,%2,%3};"
        : "+f"(c[0]), "+f"(c[1]), "+f"(c[2]), "+f"(c[3])
        : "r"(a[0]), "r"(a[1]), "r"(a[2]), "r"(a[3]), "r"(b0), "r"(b1));
}
static __device__ __forceinline__ void ldsm_x4(u32& d0, u32& d1, u32& d2, u32& d3, u32 addr) {
    asm volatile("ldmatrix.sync.aligned.m8n8.x4.shared.b16 {%0,%1,%2,%3}, [%4];"
                 : "=r"(d0), "=r"(d1), "=r"(d2), "=r"(d3) : "r"(addr));
}

__global__ __launch_bounds__(256, 2) void gemm_mma(
    float* __restrict__ out_user, float* __restrict__ out_item,
    const float* __restrict__ b_f, const float* __restrict__ b_rb,
    const float* __restrict__ b_r)
{
    __shared__ __align__(16) h16 As[128 * ASTR];
    __shared__ __align__(16) h16 Bs[128 * ASTR];

    const int tid = threadIdx.x;
    const int wid = tid >> 5, lane = tid & 31;
    const int g = lane >> 2, t = lane & 3;
    const int q = lane >> 3, rr = lane & 7;
    const int row0 = blockIdx.x * 128;
    const bool user = (blockIdx.y == 0);
    const int nsegs = user ? 2 : 1;

    const int wm0 = (wid >> 1) * 32;
    const int wn0 = (wid & 1) * 64;

    float C[2][8][4];
#pragma unroll
    for (int mt = 0; mt < 2; mt++)
#pragma unroll
        for (int nt = 0; nt < 8; nt++)
#pragma unroll
            for (int qq = 0; qq < 4; qq++) C[mt][nt][qq] = 0.f;

    const int lrow = tid >> 1;
    const int lcol = (tid & 1) * 32;
    const bool arow_ok = (row0 + lrow < NROWS);

    const u32 as_b = (u32)__cvta_generic_to_shared(As);
    const u32 bs_b = (u32)__cvta_generic_to_shared(Bs);
    u32 a_ad[2], b_ad[4];
#pragma unroll
    for (int mt = 0; mt < 2; mt++)
        a_ad[mt] = as_b + ((wm0 + mt * 16 + (q & 1) * 8 + rr) * ASTR + (q >> 1) * 8) * 2;
#pragma unroll
    for (int np = 0; np < 4; np++)
        b_ad[np] = bs_b + ((wn0 + (np * 2 + (q >> 1)) * 8 + rr) * ASTR + (q & 1) * 8) * 2;

    for (int seg = 0; seg < nsegs; seg++) {
        const int we = user ? seg : 2;
        const h16* Asrc = user ? (seg ? g_a_rb : g_a_f) : g_a_r;
        const h16* Wsrc = g_w16 + we * D * D;
#pragma unroll
        for (int st = 0; st < 2; st++) {
            const int kc = st * 64;
            // stage A and B (64-k chunk)
            uint4 av[4], wv[4];
            const h16* as_ = Asrc + (size_t)(row0 + lrow) * D + kc + lcol;
            const h16* ws_ = Wsrc + (size_t)lrow * D + kc + lcol;
#pragma unroll
            for (int qq = 0; qq < 4; qq++) {
                av[qq] = arow_ok ? *reinterpret_cast<const uint4*>(as_ + qq * 8)
                                 : make_uint4(0u, 0u, 0u, 0u);
                wv[qq] = *reinterpret_cast<const uint4*>(ws_ + qq * 8);
            }
            __syncthreads();
#pragma unroll
            for (int qq = 0; qq < 4; qq++) {
                *reinterpret_cast<uint4*>(&As[lrow * ASTR + lcol + qq * 8]) = av[qq];
                *reinterpret_cast<uint4*>(&Bs[lrow * ASTR + lcol + qq * 8]) = wv[qq];
            }
            __syncthreads();

#pragma unroll
            for (int ks = 0; ks < 4; ks++) {
                u32 af[2][4];
                ldsm_x4(af[0][0], af[0][1], af[0][2], af[0][3], a_ad[0] + ks * 32);
                ldsm_x4(af[1][0], af[1][1], af[1][2], af[1][3], a_ad[1] + ks * 32);
                u32 bf_[4][4];
#pragma unroll
                for (int np = 0; np < 4; np++)
                    ldsm_x4(bf_[np][0], bf_[np][1], bf_[np][2], bf_[np][3],
                            b_ad[np] + ks * 32);
#pragma unroll
                for (int nt = 0; nt < 8; nt++) {
                    u32 b0 = bf_[nt >> 1][(nt & 1) * 2];
                    u32 b1 = bf_[nt >> 1][(nt & 1) * 2 + 1];
                    mma_f16(C[0][nt], af[0], b0, b1);
                    mma_f16(C[1][nt], af[1], b0, b1);
                }
            }
        }
    }

    // epilogue: masked biases, direct stores
    const float* bias0 = user ? b_f : b_r;
    const int* cnt0 = user ? g_hist_f : g_hist_r;
    float* out = user ? out_user : out_item;
#pragma unroll
    for (int mt = 0; mt < 2; mt++) {
        int r0 = row0 + wm0 + mt * 16 + g;
        int r1 = r0 + 8;
        bool ok0 = (r0 < NROWS), ok1 = (r1 < NROWS);
        float m00 = (ok0 && cnt0[ok0 ? r0 : 0] > 0) ? 1.f : 0.f;
        float m01 = (ok1 && cnt0[ok1 ? r1 : 0] > 0) ? 1.f : 0.f;
        float m10 = (user && ok0 && g_hist_rb[ok0 ? r0 : 0] > 0) ? 1.f : 0.f;
        float m11 = (user && ok1 && g_hist_rb[ok1 ? r1 : 0] > 0) ? 1.f : 0.f;
#pragma unroll
        for (int nt = 0; nt < 8; nt++) {
            int col = wn0 + nt * 8 + t * 2;
            float bb0 = bias0[col], bb1 = bias0[col + 1];
            float br0 = user ? b_rb[col] : 0.f;
            float br1 = user ? b_rb[col + 1] : 0.f;
            if (ok0) {
                float2 v;
                v.x = C[mt][nt][0] + bb0 * m00 + br0 * m10;
                v.y = C[mt][nt][1] + bb1 * m00 + br1 * m10;
                *reinterpret_cast<float2*>(out + (size_t)r0 * D + col) = v;
            }
            if (ok1) {
                float2 v;
                v.x = C[mt][nt][2] + bb0 * m01 + br0 * m11;
                v.y = C[mt][nt][3] + bb1 * m01 + br1 * m11;
                *reinterpret_cast<float2*>(out + (size_t)r1 * D + col) = v;
            }
        }
    }
}

// ---------------- launch ------------------------------------------------------
extern "C" void kernel_launch(void* const* d_in, const int* in_sizes, int n_in,
                              void* d_out, int out_size)
{
    const float* feat_user = (const float*)d_in[0];
    const float* feat_item = (const float*)d_in[1];
    const float* W_f  = (const float*)d_in[2];
    const float* b_f  = (const float*)d_in[3];
    const float* W_r  = (const float*)d_in[4];
    const float* b_r  = (const float*)d_in[5];
    const float* W_rb = (const float*)d_in[6];
    const float* b_rb = (const float*)d_in[7];
    const int* src_f  = (const int*)d_in[8];
    const int* dst_f  = (const int*)d_in[9];
    const int* src_r  = (const int*)d_in[10];
    const int* dst_r  = (const int*)d_in[11];
    const int* src_rb = (const int*)d_in[12];
    const int* dst_rb = (const int*)d_in[13];
    const int E_f  = in_sizes[8];
    const int E_rb = in_sizes[12];
    const int E_r  = in_sizes[10];

    float* out_user = (float*)d_out;
    float* out_item = (float*)d_out + (size_t)NU * D;

    int Emax = E_f > E_rb ? E_f : E_rb;
    if (E_r > Emax) Emax = E_r;

    zero_hist_kernel<<<(NU + 255) / 256, 256>>>();

    {
        dim3 g((Emax + 255) / 256, 3);
        hist3_kernel<<<g, 256>>>(dst_f, dst_rb, dst_r, E_f, E_rb, E_r);
    }

    wprep_kernel<<<3, 256>>>(W_f, W_rb, W_r);

    {
        dim3 g(SCAN_NB, 3);
        scan_p1<<<g, 256>>>();
        scan_p2<<<1, 3>>>();
        scan_p3<<<g, 256>>>();
    }

    {
        dim3 g((Emax + 255) / 256, 3);
        permute3_kernel<<<g, 256>>>(src_f, dst_f, src_rb, dst_rb, src_r, dst_r,
                                    E_f, E_rb, E_r);
    }

    {
        dim3 g((NROWS * 32 + 255) / 256, 3);
        gather3_kernel<<<g, 256>>>((const float4*)feat_user,
                                   (const float4*)feat_item);
    }

    {
        dim3 g((NROWS + 127) / 128, 2);
        gemm_mma<<<g, 256>>>(out_user, out_item, b_f, b_rb, b_r);
    }
}